// round 10
// baseline (speedup 1.0000x reference)
#include <cuda_runtime.h>
#include <cuda_fp16.h>
#include <math.h>

#define NN 100000
#define CC 16
#define EE 3200000
#define FF 512
#define HH 64
#define VN (2*NN)

#define NBLK2 196        // ceil(VN/1024)
#define EB4   6250       // 2*EE/(256*4)
#define PB2   25000      // VN warps / 8 warps-per-block
#define FB    6250       // NN*CC/256
#define GEMM_BLKS 782    // ceil(NN/128)
#define MASKW 3125       // NN/32

// ---------------- scratch (device globals: allocation-free) ----------------
__device__ int      g_cnt[VN];
__device__ int      g_rowptr[VN + 1];
__device__ int      g_wp[VN];
__device__ int      g_blksum[256];
__device__ int      g_arrive;
__device__ unsigned g_trainbit[MASKW];
__device__ uint2    g_edge8[2 * EE];       // {src, half2(exp(e_l0), exp(e_l1))}
__device__ uint4    g_li16[NN * 2];        // label_init fp16 (2 uint4 = 16 halves/row)
__device__ uint4    g_oh16[NN * 2];        // one_hot fp16
__device__ uint4    g_h016[VN * 2];        // layer-0 output fp16, both graphs
__device__ float    g_hg[VN * CC];         // layer-1 output fp32, both graphs
__device__ float    g_hidden[NN * HH];     // MLP hidden (relu(X@W1+b1))
__device__ float    g_mlp[NN * CC];        // MLP2 output (hidden@W2+b2)
__device__ __half   g_w1h[HH * FF];        // W1 transposed [n][k], fp16

// ---------------- helpers ----------------
__device__ __forceinline__ void mma_f16(float c[4], unsigned a0, unsigned a1,
                                        unsigned a2, unsigned a3,
                                        unsigned b0, unsigned b1) {
    asm volatile("mma.sync.aligned.m16n8k16.row.col.f32.f16.f16.f32 "
                 "{%0,%1,%2,%3}, {%4,%5,%6,%7}, {%8,%9}, {%0,%1,%2,%3};"
                 : "+f"(c[0]), "+f"(c[1]), "+f"(c[2]), "+f"(c[3])
                 : "r"(a0), "r"(a1), "r"(a2), "r"(a3), "r"(b0), "r"(b1));
}
__device__ __forceinline__ bool is_train(int d) {
    return (g_trainbit[d >> 5] >> (d & 31)) & 1u;
}

// ---------------- prep: bitmask + W1 fp16 transpose + fp16 conversions ------
__global__ __launch_bounds__(256) void prep_kernel(const int* __restrict__ train,
                                                   const float* __restrict__ w1,
                                                   const float* __restrict__ label_init,
                                                   const float* __restrict__ one_hot) {
    int i = blockIdx.x * blockDim.x + threadIdx.x;     // grid covers NN*CC/2 = 800000
    if (i < NN * CC / 2) {
        float2 li = ((const float2*)label_init)[i];
        float2 oh = ((const float2*)one_hot)[i];
        __half2 l2 = __floats2half2_rn(li.x, li.y);
        __half2 o2 = __floats2half2_rn(oh.x, oh.y);
        ((unsigned*)g_li16)[i] = *(unsigned*)&l2;
        ((unsigned*)g_oh16)[i] = *(unsigned*)&o2;
    }
    if (i < FF * HH) {
        int k = i >> 6, n = i & 63;                    // w1 is [k][n], HH=64
        g_w1h[n * FF + k] = __float2half(w1[i]);
    }
    if (i < VN) g_cnt[i] = 0;
    if (i == 0) g_arrive = 0;
    if (i < MASKW) {
        unsigned m = 0;
        #pragma unroll 8
        for (int b = 0; b < 32; b++)
            m |= (train[i * 32 + b] != 0 ? 1u : 0u) << b;
        g_trainbit[i] = m;
    }
}

// ---------------- hist (bitmask + int4 vectorized) --------------------------
__global__ __launch_bounds__(256) void hist_kernel(const int* __restrict__ dst) {
    int t = blockIdx.x * 256 + threadIdx.x;            // covers 4 edges
    int4 d4 = ((const int4*)dst)[t];
    int base = ((t << 2) >= EE) ? NN : 0;              // EE % 4 == 0
    if (!is_train(d4.x)) atomicAdd(&g_cnt[base + d4.x], 1);
    if (!is_train(d4.y)) atomicAdd(&g_cnt[base + d4.y], 1);
    if (!is_train(d4.z)) atomicAdd(&g_cnt[base + d4.z], 1);
    if (!is_train(d4.w)) atomicAdd(&g_cnt[base + d4.w], 1);
}

// ---------------- single-launch scan (grid barrier; 196 blocks all resident)
__global__ __launch_bounds__(1024) void scan_fused_kernel() {
    __shared__ int warpsum[32];
    __shared__ int s2[256];
    int b = blockIdx.x, t = threadIdx.x;
    int lane = t & 31, wid = t >> 5;
    int i = b * 1024 + t;
    int c = (i < VN) ? g_cnt[i] : 0;

    int v = c;
    #pragma unroll
    for (int off = 1; off < 32; off <<= 1) {
        int u = __shfl_up_sync(0xFFFFFFFFu, v, off);
        if (lane >= off) v += u;
    }
    if (lane == 31) warpsum[wid] = v;
    __syncthreads();
    if (wid == 0) {
        int wv = warpsum[lane];
        #pragma unroll
        for (int off = 1; off < 32; off <<= 1) {
            int u = __shfl_up_sync(0xFFFFFFFFu, wv, off);
            if (lane >= off) wv += u;
        }
        warpsum[lane] = wv;
    }
    __syncthreads();
    int incl_local = v + ((wid > 0) ? warpsum[wid - 1] : 0);
    int total = warpsum[31];

    if (t == 0) {
        g_blksum[b] = total;
        __threadfence();
        atomicAdd(&g_arrive, 1);
        while (atomicAdd(&g_arrive, 0) < NBLK2) { }
    }
    __syncthreads();

    if (t < 256) s2[t] = (t < NBLK2) ? g_blksum[t] : 0;
    __syncthreads();
    #pragma unroll
    for (int off = 1; off < 256; off <<= 1) {
        int u = 0;
        if (t < 256 && t >= off) u = s2[t - off];
        __syncthreads();
        if (t < 256) s2[t] += u;
        __syncthreads();
    }
    int prev = (b > 0) ? s2[b - 1] : 0;
    if (i < VN) {
        int incl = incl_local + prev;
        g_rowptr[i + 1] = incl;
        g_wp[i] = incl - c;
    }
    if (i == 0) g_rowptr[0] = 0;
}

// ---------------- standalone CSR scatter (high occupancy, low regs) ---------
__global__ __launch_bounds__(256) void scatter_kernel(
        const int* __restrict__ src, const int* __restrict__ dst,
        const float* __restrict__ e_edge) {
    int t = blockIdx.x * 256 + threadIdx.x;            // covers 4 edges
    int4   s4 = ((const int4*)src)[t];
    int4   d4 = ((const int4*)dst)[t];
    float4 e0 = ((const float4*)e_edge)[t];
    float4 e1 = ((const float4*)(e_edge + 2 * (size_t)EE))[t];
    int base = ((t << 2) >= EE) ? NN : 0;
    // softmax max-shift cancels; exp(|e|<6) safe; fp16 range ok (exp<=e^6~403)
    if (!is_train(d4.x)) {
        int p = atomicAdd(&g_wp[base + d4.x], 1);
        __half2 w = __floats2half2_rn(__expf(e0.x), __expf(e1.x));
        g_edge8[p] = make_uint2((unsigned)s4.x, *(unsigned*)&w);
    }
    if (!is_train(d4.y)) {
        int p = atomicAdd(&g_wp[base + d4.y], 1);
        __half2 w = __floats2half2_rn(__expf(e0.y), __expf(e1.y));
        g_edge8[p] = make_uint2((unsigned)s4.y, *(unsigned*)&w);
    }
    if (!is_train(d4.z)) {
        int p = atomicAdd(&g_wp[base + d4.z], 1);
        __half2 w = __floats2half2_rn(__expf(e0.z), __expf(e1.z));
        g_edge8[p] = make_uint2((unsigned)s4.z, *(unsigned*)&w);
    }
    if (!is_train(d4.w)) {
        int p = atomicAdd(&g_wp[base + d4.w], 1);
        __half2 w = __floats2half2_rn(__expf(e0.w), __expf(e1.w));
        g_edge8[p] = make_uint2((unsigned)s4.w, *(unsigned*)&w);
    }
}

// ---------------- shared prop body (gather, warp-per-vnode, dual-edge) ------
template <int LAYER>
__device__ __forceinline__ void prop_body(int v, int lane,
                                          const float* __restrict__ one_hot) {
    int n = (v < NN) ? v : v - NN;

    if (is_train(n)) {
        if (LAYER == 0) {
            if (lane < 2) g_h016[(size_t)v * 2 + lane] = g_oh16[(size_t)n * 2 + lane];
        } else {
            if (lane < CC) g_hg[(size_t)v * CC + lane] = one_hot[(size_t)n * CC + lane];
        }
        return;
    }

    const uint4* hbase = (LAYER == 0) ? g_li16
                                      : (g_h016 + ((v < NN) ? 0 : (size_t)NN * 2));
    int beg = g_rowptr[v], end = g_rowptr[v + 1];
    int half = lane & 1;

    float a[8];
    #pragma unroll
    for (int q = 0; q < 8; q++) a[q] = 0.f;
    float sw = 0.f;

    for (int j = beg + (lane >> 1); j < end; j += 32) {
        uint2 r1 = g_edge8[j];
        int j2 = j + 16;
        uint2 r2 = (j2 < end) ? g_edge8[j2] : make_uint2(r1.x, 0u);  // w=0 pad
        int s1 = (int)r1.x, s2 = (int)r2.x;
        __half2 wh1 = *(__half2*)&r1.y, wh2 = *(__half2*)&r2.y;
        float w1 = (LAYER == 0) ? __low2float(wh1) : __high2float(wh1);
        float w2 = (LAYER == 0) ? __low2float(wh2) : __high2float(wh2);
        uint4 u1 = hbase[(size_t)s1 * 2 + half];
        uint4 u2 = hbase[(size_t)s2 * 2 + half];
        {
            float2 f0 = __half22float2(*(__half2*)&u1.x);
            float2 f1 = __half22float2(*(__half2*)&u1.y);
            float2 f2 = __half22float2(*(__half2*)&u1.z);
            float2 f3 = __half22float2(*(__half2*)&u1.w);
            a[0] = fmaf(w1, f0.x, a[0]); a[1] = fmaf(w1, f0.y, a[1]);
            a[2] = fmaf(w1, f1.x, a[2]); a[3] = fmaf(w1, f1.y, a[3]);
            a[4] = fmaf(w1, f2.x, a[4]); a[5] = fmaf(w1, f2.y, a[5]);
            a[6] = fmaf(w1, f3.x, a[6]); a[7] = fmaf(w1, f3.y, a[7]);
        }
        {
            float2 f0 = __half22float2(*(__half2*)&u2.x);
            float2 f1 = __half22float2(*(__half2*)&u2.y);
            float2 f2 = __half22float2(*(__half2*)&u2.z);
            float2 f3 = __half22float2(*(__half2*)&u2.w);
            a[0] = fmaf(w2, f0.x, a[0]); a[1] = fmaf(w2, f0.y, a[1]);
            a[2] = fmaf(w2, f1.x, a[2]); a[3] = fmaf(w2, f1.y, a[3]);
            a[4] = fmaf(w2, f2.x, a[4]); a[5] = fmaf(w2, f2.y, a[5]);
            a[6] = fmaf(w2, f3.x, a[6]); a[7] = fmaf(w2, f3.y, a[7]);
        }
        sw += w1 + w2;
    }
    #pragma unroll
    for (int off = 2; off < 32; off <<= 1) {
        #pragma unroll
        for (int q = 0; q < 8; q++)
            a[q] += __shfl_xor_sync(0xFFFFFFFFu, a[q], off);
        sw += __shfl_xor_sync(0xFFFFFFFFu, sw, off);
    }
    if (lane < 2) {
        float inv = (sw > 0.f) ? (1.f / sw) : 0.f;
        #pragma unroll
        for (int q = 0; q < 8; q++) a[q] *= inv;
        if (LAYER == 0) {
            __half2 o0 = __floats2half2_rn(a[0], a[1]);
            __half2 o1 = __floats2half2_rn(a[2], a[3]);
            __half2 o2 = __floats2half2_rn(a[4], a[5]);
            __half2 o3 = __floats2half2_rn(a[6], a[7]);
            uint4 u;
            u.x = *(unsigned*)&o0; u.y = *(unsigned*)&o1;
            u.z = *(unsigned*)&o2; u.w = *(unsigned*)&o3;
            g_h016[(size_t)v * 2 + half] = u;
        } else {
            float* op = g_hg + (size_t)v * CC + half * 8;
            ((float4*)op)[0] = make_float4(a[0], a[1], a[2], a[3]);
            ((float4*)op)[1] = make_float4(a[4], a[5], a[6], a[7]);
        }
    }
}

// ---------------- launch A: fp16 GEMM blocks + prop<0> blocks ---------------
__global__ __launch_bounds__(256) void prop0_gemm_kernel(
        const float* __restrict__ one_hot,
        const float* __restrict__ X, const float* __restrict__ bias) {
    __shared__ __align__(16) __half Xs[128][24];   // GEMM only
    __shared__ __align__(16) __half Ws[64][24];

    if (blockIdx.x < GEMM_BLKS) {
        int tid = threadIdx.x;
        int lane = tid & 31;
        int gid = lane >> 2, tig = lane & 3;
        int m0 = (tid >> 5) * 16;
        int n0 = blockIdx.x * 128;

        float acc[8][4];
        #pragma unroll
        for (int nt = 0; nt < 8; nt++)
            #pragma unroll
            for (int r = 0; r < 4; r++) acc[nt][r] = 0.f;

        for (int k0 = 0; k0 < FF; k0 += 16) {
            #pragma unroll
            for (int r = 0; r < 2; r++) {
                int idx = tid + r * 256;
                int row = idx >> 2, kq = idx & 3;
                int gn = n0 + row;
                float4 xv = make_float4(0.f, 0.f, 0.f, 0.f);
                if (gn < NN) xv = *(const float4*)(X + (size_t)gn * FF + k0 + kq * 4);
                __half2 h0 = __floats2half2_rn(xv.x, xv.y);
                __half2 h1 = __floats2half2_rn(xv.z, xv.w);
                *(uint2*)&Xs[row][kq * 4] = make_uint2(*(unsigned*)&h0, *(unsigned*)&h1);
            }
            if (tid < 128) {
                int row = tid >> 1, part = tid & 1;
                uint4 wv = *(const uint4*)(g_w1h + (size_t)row * FF + k0 + part * 8);
                *(uint4*)&Ws[row][part * 8] = wv;
            }
            __syncthreads();
            unsigned a0 = *(unsigned*)&Xs[m0 + gid    ][2 * tig    ];
            unsigned a1 = *(unsigned*)&Xs[m0 + gid + 8][2 * tig    ];
            unsigned a2 = *(unsigned*)&Xs[m0 + gid    ][2 * tig + 8];
            unsigned a3 = *(unsigned*)&Xs[m0 + gid + 8][2 * tig + 8];
            #pragma unroll
            for (int nt = 0; nt < 8; nt++) {
                unsigned b0 = *(unsigned*)&Ws[nt * 8 + gid][2 * tig    ];
                unsigned b1 = *(unsigned*)&Ws[nt * 8 + gid][2 * tig + 8];
                mma_f16(acc[nt], a0, a1, a2, a3, b0, b1);
            }
            __syncthreads();
        }

        #pragma unroll
        for (int rr = 0; rr < 2; rr++) {
            int row = n0 + m0 + rr * 8 + gid;
            if (row >= NN) continue;
            #pragma unroll
            for (int nt = 0; nt < 8; nt++) {
                int col = nt * 8 + 2 * tig;
                float v0 = fmaxf(acc[nt][rr * 2 + 0] + bias[col], 0.f);
                float v1 = fmaxf(acc[nt][rr * 2 + 1] + bias[col + 1], 0.f);
                *(float2*)(g_hidden + (size_t)row * HH + col) = make_float2(v0, v1);
            }
        }
        return;
    }

    int v = ((blockIdx.x - GEMM_BLKS) * blockDim.x + threadIdx.x) >> 5;
    if (v >= VN) return;
    prop_body<0>(v, threadIdx.x & 31, one_hot);
}

// ---------------- launch B: MLP2 GEMV blocks + prop<1> blocks ---------------
__global__ __launch_bounds__(256) void prop1_mlp2_kernel(
        const float* __restrict__ one_hot,
        const float* __restrict__ w2, const float* __restrict__ b2) {
    __shared__ float sw2[HH * CC];

    if (blockIdx.x < FB) {
        for (int i = threadIdx.x; i < HH * CC; i += 256) sw2[i] = w2[i];
        __syncthreads();
        int idx = blockIdx.x * 256 + threadIdx.x;      // < NN*CC
        int n = idx >> 4, c = idx & 15;
        float m = b2[c];
        const float4* hr = (const float4*)(g_hidden + (size_t)n * HH);
        #pragma unroll
        for (int k = 0; k < 16; k++) {
            float4 hv = hr[k];
            m = fmaf(hv.x, sw2[(4 * k + 0) * CC + c], m);
            m = fmaf(hv.y, sw2[(4 * k + 1) * CC + c], m);
            m = fmaf(hv.z, sw2[(4 * k + 2) * CC + c], m);
            m = fmaf(hv.w, sw2[(4 * k + 3) * CC + c], m);
        }
        g_mlp[idx] = m;
        return;
    }

    int v = ((blockIdx.x - FB) * blockDim.x + threadIdx.x) >> 5;
    if (v >= VN) return;
    prop_body<1>(v, threadIdx.x & 31, one_hot);
}

// ---------------- final: attention combine + residual mix -------------------
__global__ __launch_bounds__(256) void final_kernel(const float* __restrict__ att,
                                                    const float* __restrict__ alpha,
                                                    float* __restrict__ out) {
    int idx = blockIdx.x * blockDim.x + threadIdx.x;
    if (idx >= NN * CC) return;
    int n = idx >> 4, c = idx & 15;

    float a0 = att[n * 2 + 0], a1 = att[n * 2 + 1];
    float mx = fmaxf(a0, a1);
    float e0 = expf(a0 - mx), e1 = expf(a1 - mx);
    float inv = 1.f / (e0 + e1);

    float sa = 1.f / (1.f + expf(-alpha[n]));
    float logits = g_hg[idx] * (e0 * inv) + g_hg[(size_t)(NN + n) * CC + c] * (e1 * inv);
    out[idx] = sa * logits + (1.f - sa) * g_mlp[idx];
}

// ---------------- launcher ----------------
extern "C" void kernel_launch(void* const* d_in, const int* in_sizes, int n_in,
                              void* d_out, int out_size) {
    (void)in_sizes; (void)n_in; (void)out_size;
    const float* features   = (const float*)d_in[0];
    const float* label_init = (const float*)d_in[1];
    const float* one_hot    = (const float*)d_in[2];
    const float* alpha      = (const float*)d_in[3];
    const float* attention  = (const float*)d_in[4];
    const float* e_edge     = (const float*)d_in[5];
    const float* w1         = (const float*)d_in[6];
    const float* b1         = (const float*)d_in[7];
    const float* w2         = (const float*)d_in[8];
    const float* b2         = (const float*)d_in[9];
    const int*   src        = (const int*)d_in[10];
    const int*   dst        = (const int*)d_in[11];
    const int*   train      = (const int*)d_in[12];
    float*       out        = (float*)d_out;

    prep_kernel<<<(NN * CC / 2 + 255) / 256, 256>>>(train, w1, label_init, one_hot); // 1
    hist_kernel<<<EB4, 256>>>(dst);                                                  // 2
    scan_fused_kernel<<<NBLK2, 1024>>>();                                            // 3
    scatter_kernel<<<EB4, 256>>>(src, dst, e_edge);                                  // 4 (ncu)
    prop0_gemm_kernel<<<GEMM_BLKS + PB2, 256>>>(one_hot, features, b1);              // 5
    prop1_mlp2_kernel<<<FB + PB2, 256>>>(one_hot, w2, b2);                           // 6
    final_kernel<<<FB, 256>>>(attention, alpha, out);                                // 7
}

// round 11
// speedup vs baseline: 1.0411x; 1.0411x over previous
#include <cuda_runtime.h>
#include <cuda_fp16.h>
#include <math.h>

#define NN 100000
#define CC 16
#define EE 3200000
#define FF 512
#define HH 64
#define VN (2*NN)

#define NBLK2 196        // ceil(VN/1024)
#define EB4   6250       // 2*EE/(256*4)
#define PB2   25000      // VN warps / 8 warps-per-block
#define FB    6250       // NN*CC/256
#define GEMM_BLKS 782    // ceil(NN/128)
#define MASKW 3125       // NN/32
#define CONVB 3125       // conversion blocks (800000/256)

// ---------------- scratch (device globals: allocation-free) ----------------
__device__ int      g_cnt[VN];
__device__ int      g_rowptr[VN + 1];
__device__ int      g_wp[VN];
__device__ int      g_blksum[256];
__device__ int      g_arrive;
__device__ unsigned g_trainbit[MASKW];
__device__ uint2    g_edge8[2 * EE];       // {src, half2(exp(e_l0), exp(e_l1))}
__device__ uint4    g_li16[NN * 2];        // label_init fp16 (2 uint4 = 16 halves/row)
__device__ uint4    g_oh16[NN * 2];        // one_hot fp16
__device__ uint4    g_h016[VN * 2];        // layer-0 output fp16, both graphs
__device__ float    g_hg[VN * CC];         // layer-1 output fp32, both graphs
__device__ float    g_hidden[NN * HH];     // MLP hidden (relu(X@W1+b1))
__device__ __half   g_w1h[HH * FF];        // W1 transposed [n][k], fp16

// ---------------- helpers ----------------
__device__ __forceinline__ void mma_f16(float c[4], unsigned a0, unsigned a1,
                                        unsigned a2, unsigned a3,
                                        unsigned b0, unsigned b1) {
    asm volatile("mma.sync.aligned.m16n8k16.row.col.f32.f16.f16.f32 "
                 "{%0,%1,%2,%3}, {%4,%5,%6,%7}, {%8,%9}, {%0,%1,%2,%3};"
                 : "+f"(c[0]), "+f"(c[1]), "+f"(c[2]), "+f"(c[3])
                 : "r"(a0), "r"(a1), "r"(a2), "r"(a3), "r"(b0), "r"(b1));
}
__device__ __forceinline__ bool is_train(int d) {
    return (g_trainbit[d >> 5] >> (d & 31)) & 1u;
}

// ---------------- mask: train bitmask + counters reset ----------------------
__global__ __launch_bounds__(256) void mask_kernel(const int* __restrict__ train) {
    int i = blockIdx.x * blockDim.x + threadIdx.x;     // grid covers VN
    if (i < VN) g_cnt[i] = 0;
    if (i == 0) g_arrive = 0;
    if (i < MASKW) {
        unsigned m = 0;
        #pragma unroll 8
        for (int b = 0; b < 32; b++)
            m |= (train[i * 32 + b] != 0 ? 1u : 0u) << b;
        g_trainbit[i] = m;
    }
}

// ---------------- hist (bitmask) + fp16/w1 conversions, one launch ----------
__global__ __launch_bounds__(256) void histconv_kernel(const int* __restrict__ dst,
                                                       const float* __restrict__ w1,
                                                       const float* __restrict__ label_init,
                                                       const float* __restrict__ one_hot) {
    if (blockIdx.x < EB4) {
        int t = blockIdx.x * 256 + threadIdx.x;        // covers 4 edges
        int4 d4 = ((const int4*)dst)[t];
        int base = ((t << 2) >= EE) ? NN : 0;          // EE % 4 == 0
        if (!is_train(d4.x)) atomicAdd(&g_cnt[base + d4.x], 1);
        if (!is_train(d4.y)) atomicAdd(&g_cnt[base + d4.y], 1);
        if (!is_train(d4.z)) atomicAdd(&g_cnt[base + d4.z], 1);
        if (!is_train(d4.w)) atomicAdd(&g_cnt[base + d4.w], 1);
        return;
    }
    int i = (blockIdx.x - EB4) * 256 + threadIdx.x;    // < 800000
    {
        float2 li = ((const float2*)label_init)[i];
        float2 oh = ((const float2*)one_hot)[i];
        __half2 l2 = __floats2half2_rn(li.x, li.y);
        __half2 o2 = __floats2half2_rn(oh.x, oh.y);
        ((unsigned*)g_li16)[i] = *(unsigned*)&l2;
        ((unsigned*)g_oh16)[i] = *(unsigned*)&o2;
    }
    if (i < FF * HH) {
        int k = i >> 6, n = i & 63;                    // w1 is [k][n], HH=64
        g_w1h[n * FF + k] = __float2half(w1[i]);
    }
}

// ---------------- single-launch scan (grid barrier; 196 blocks all resident)
__global__ __launch_bounds__(1024) void scan_fused_kernel() {
    __shared__ int warpsum[32];
    __shared__ int s2[256];
    int b = blockIdx.x, t = threadIdx.x;
    int lane = t & 31, wid = t >> 5;
    int i = b * 1024 + t;
    int c = (i < VN) ? g_cnt[i] : 0;

    int v = c;
    #pragma unroll
    for (int off = 1; off < 32; off <<= 1) {
        int u = __shfl_up_sync(0xFFFFFFFFu, v, off);
        if (lane >= off) v += u;
    }
    if (lane == 31) warpsum[wid] = v;
    __syncthreads();
    if (wid == 0) {
        int wv = warpsum[lane];
        #pragma unroll
        for (int off = 1; off < 32; off <<= 1) {
            int u = __shfl_up_sync(0xFFFFFFFFu, wv, off);
            if (lane >= off) wv += u;
        }
        warpsum[lane] = wv;
    }
    __syncthreads();
    int incl_local = v + ((wid > 0) ? warpsum[wid - 1] : 0);
    int total = warpsum[31];

    if (t == 0) {
        g_blksum[b] = total;
        __threadfence();
        atomicAdd(&g_arrive, 1);
        while (atomicAdd(&g_arrive, 0) < NBLK2) { }
    }
    __syncthreads();

    if (t < 256) s2[t] = (t < NBLK2) ? g_blksum[t] : 0;
    __syncthreads();
    #pragma unroll
    for (int off = 1; off < 256; off <<= 1) {
        int u = 0;
        if (t < 256 && t >= off) u = s2[t - off];
        __syncthreads();
        if (t < 256) s2[t] += u;
        __syncthreads();
    }
    int prev = (b > 0) ? s2[b - 1] : 0;
    if (i < VN) {
        int incl = incl_local + prev;
        g_rowptr[i + 1] = incl;
        g_wp[i] = incl - c;
    }
    if (i == 0) g_rowptr[0] = 0;
}

// ------- fused SG: fp16 GEMM + CSR scatter, roles INTERLEAVED (b%9==0) ------
__global__ __launch_bounds__(256) void scatter_gemm_kernel(
        const int* __restrict__ src, const int* __restrict__ dst,
        const float* __restrict__ e_edge,
        const float* __restrict__ X, const float* __restrict__ bias) {
    __shared__ __align__(16) __half Xs[128][24];   // [row][k], 48B stride
    __shared__ __align__(16) __half Ws[64][24];    // [n][k]

    int b = blockIdx.x;
    int g = b / 9, r = b - g * 9;

    if (r == 0 && g < GEMM_BLKS) {
        int tid = threadIdx.x;
        int lane = tid & 31;
        int gid = lane >> 2, tig = lane & 3;
        int m0 = (tid >> 5) * 16;
        int n0 = g * 128;

        float acc[8][4];
        #pragma unroll
        for (int nt = 0; nt < 8; nt++)
            #pragma unroll
            for (int q = 0; q < 4; q++) acc[nt][q] = 0.f;

        for (int k0 = 0; k0 < FF; k0 += 16) {
            #pragma unroll
            for (int rr = 0; rr < 2; rr++) {
                int idx = tid + rr * 256;
                int row = idx >> 2, kq = idx & 3;
                int gn = n0 + row;
                float4 xv = make_float4(0.f, 0.f, 0.f, 0.f);
                if (gn < NN) xv = *(const float4*)(X + (size_t)gn * FF + k0 + kq * 4);
                __half2 h0 = __floats2half2_rn(xv.x, xv.y);
                __half2 h1 = __floats2half2_rn(xv.z, xv.w);
                *(uint2*)&Xs[row][kq * 4] = make_uint2(*(unsigned*)&h0, *(unsigned*)&h1);
            }
            if (tid < 128) {
                int row = tid >> 1, part = tid & 1;
                uint4 wv = *(const uint4*)(g_w1h + (size_t)row * FF + k0 + part * 8);
                *(uint4*)&Ws[row][part * 8] = wv;
            }
            __syncthreads();
            unsigned a0 = *(unsigned*)&Xs[m0 + gid    ][2 * tig    ];
            unsigned a1 = *(unsigned*)&Xs[m0 + gid + 8][2 * tig    ];
            unsigned a2 = *(unsigned*)&Xs[m0 + gid    ][2 * tig + 8];
            unsigned a3 = *(unsigned*)&Xs[m0 + gid + 8][2 * tig + 8];
            #pragma unroll
            for (int nt = 0; nt < 8; nt++) {
                unsigned b0 = *(unsigned*)&Ws[nt * 8 + gid][2 * tig    ];
                unsigned b1 = *(unsigned*)&Ws[nt * 8 + gid][2 * tig + 8];
                mma_f16(acc[nt], a0, a1, a2, a3, b0, b1);
            }
            __syncthreads();
        }

        #pragma unroll
        for (int rr = 0; rr < 2; rr++) {
            int row = n0 + m0 + rr * 8 + gid;
            if (row >= NN) continue;
            #pragma unroll
            for (int nt = 0; nt < 8; nt++) {
                int col = nt * 8 + 2 * tig;
                float v0 = fmaxf(acc[nt][rr * 2 + 0] + bias[col], 0.f);
                float v1 = fmaxf(acc[nt][rr * 2 + 1] + bias[col + 1], 0.f);
                *(float2*)(g_hidden + (size_t)row * HH + col) = make_float2(v0, v1);
            }
        }
        return;
    }

    // ---- scatter role: contiguous scatter index skipping gemm slots ----
    int nskip = (b + 8) / 9;                           // # gemm slots <= b
    if (nskip > GEMM_BLKS) nskip = GEMM_BLKS;
    int t = (b - nskip) * 256 + threadIdx.x;           // covers 4 edges
    int4   s4 = ((const int4*)src)[t];
    int4   d4 = ((const int4*)dst)[t];
    float4 e0 = ((const float4*)e_edge)[t];
    float4 e1 = ((const float4*)(e_edge + 2 * (size_t)EE))[t];
    int base = ((t << 2) >= EE) ? NN : 0;
    // softmax max-shift cancels; exp(|e|<6) safe; fp16 range ok
    if (!is_train(d4.x)) {
        int p = atomicAdd(&g_wp[base + d4.x], 1);
        __half2 w = __floats2half2_rn(__expf(e0.x), __expf(e1.x));
        g_edge8[p] = make_uint2((unsigned)s4.x, *(unsigned*)&w);
    }
    if (!is_train(d4.y)) {
        int p = atomicAdd(&g_wp[base + d4.y], 1);
        __half2 w = __floats2half2_rn(__expf(e0.y), __expf(e1.y));
        g_edge8[p] = make_uint2((unsigned)s4.y, *(unsigned*)&w);
    }
    if (!is_train(d4.z)) {
        int p = atomicAdd(&g_wp[base + d4.z], 1);
        __half2 w = __floats2half2_rn(__expf(e0.z), __expf(e1.z));
        g_edge8[p] = make_uint2((unsigned)s4.z, *(unsigned*)&w);
    }
    if (!is_train(d4.w)) {
        int p = atomicAdd(&g_wp[base + d4.w], 1);
        __half2 w = __floats2half2_rn(__expf(e0.w), __expf(e1.w));
        g_edge8[p] = make_uint2((unsigned)s4.w, *(unsigned*)&w);
    }
}

// ---- propagate (gather, warp-per-vnode, 2 lanes/edge, dual-edge MLP) -------
template <int LAYER>
__global__ __launch_bounds__(256) void prop_kernel(const float* __restrict__ one_hot) {
    int v    = (blockIdx.x * blockDim.x + threadIdx.x) >> 5;
    int lane = threadIdx.x & 31;
    if (v >= VN) return;
    int n = (v < NN) ? v : v - NN;

    if (is_train(n)) {
        if (LAYER == 0) {
            if (lane < 2) g_h016[(size_t)v * 2 + lane] = g_oh16[(size_t)n * 2 + lane];
        } else {
            if (lane < CC) g_hg[(size_t)v * CC + lane] = one_hot[(size_t)n * CC + lane];
        }
        return;
    }

    const uint4* hbase = (LAYER == 0) ? g_li16
                                      : (g_h016 + ((v < NN) ? 0 : (size_t)NN * 2));
    int beg = g_rowptr[v], end = g_rowptr[v + 1];
    int half = lane & 1;

    float a[8];
    #pragma unroll
    for (int q = 0; q < 8; q++) a[q] = 0.f;
    float sw = 0.f;

    for (int j = beg + (lane >> 1); j < end; j += 32) {
        uint2 r1 = g_edge8[j];
        int j2 = j + 16;
        uint2 r2 = (j2 < end) ? g_edge8[j2] : make_uint2(r1.x, 0u);  // w=0 pad
        int s1 = (int)r1.x, s2 = (int)r2.x;
        __half2 wh1 = *(__half2*)&r1.y, wh2 = *(__half2*)&r2.y;
        float w1 = (LAYER == 0) ? __low2float(wh1) : __high2float(wh1);
        float w2 = (LAYER == 0) ? __low2float(wh2) : __high2float(wh2);
        uint4 u1 = hbase[(size_t)s1 * 2 + half];
        uint4 u2 = hbase[(size_t)s2 * 2 + half];
        {
            float2 f0 = __half22float2(*(__half2*)&u1.x);
            float2 f1 = __half22float2(*(__half2*)&u1.y);
            float2 f2 = __half22float2(*(__half2*)&u1.z);
            float2 f3 = __half22float2(*(__half2*)&u1.w);
            a[0] = fmaf(w1, f0.x, a[0]); a[1] = fmaf(w1, f0.y, a[1]);
            a[2] = fmaf(w1, f1.x, a[2]); a[3] = fmaf(w1, f1.y, a[3]);
            a[4] = fmaf(w1, f2.x, a[4]); a[5] = fmaf(w1, f2.y, a[5]);
            a[6] = fmaf(w1, f3.x, a[6]); a[7] = fmaf(w1, f3.y, a[7]);
        }
        {
            float2 f0 = __half22float2(*(__half2*)&u2.x);
            float2 f1 = __half22float2(*(__half2*)&u2.y);
            float2 f2 = __half22float2(*(__half2*)&u2.z);
            float2 f3 = __half22float2(*(__half2*)&u2.w);
            a[0] = fmaf(w2, f0.x, a[0]); a[1] = fmaf(w2, f0.y, a[1]);
            a[2] = fmaf(w2, f1.x, a[2]); a[3] = fmaf(w2, f1.y, a[3]);
            a[4] = fmaf(w2, f2.x, a[4]); a[5] = fmaf(w2, f2.y, a[5]);
            a[6] = fmaf(w2, f3.x, a[6]); a[7] = fmaf(w2, f3.y, a[7]);
        }
        sw += w1 + w2;
    }
    #pragma unroll
    for (int off = 2; off < 32; off <<= 1) {
        #pragma unroll
        for (int q = 0; q < 8; q++)
            a[q] += __shfl_xor_sync(0xFFFFFFFFu, a[q], off);
        sw += __shfl_xor_sync(0xFFFFFFFFu, sw, off);
    }
    if (lane < 2) {
        float inv = (sw > 0.f) ? (1.f / sw) : 0.f;
        #pragma unroll
        for (int q = 0; q < 8; q++) a[q] *= inv;
        if (LAYER == 0) {
            __half2 o0 = __floats2half2_rn(a[0], a[1]);
            __half2 o1 = __floats2half2_rn(a[2], a[3]);
            __half2 o2 = __floats2half2_rn(a[4], a[5]);
            __half2 o3 = __floats2half2_rn(a[6], a[7]);
            uint4 u;
            u.x = *(unsigned*)&o0; u.y = *(unsigned*)&o1;
            u.z = *(unsigned*)&o2; u.w = *(unsigned*)&o3;
            g_h016[(size_t)v * 2 + half] = u;
        } else {
            float* op = g_hg + (size_t)v * CC + half * 8;
            ((float4*)op)[0] = make_float4(a[0], a[1], a[2], a[3]);
            ((float4*)op)[1] = make_float4(a[4], a[5], a[6], a[7]);
        }
    }
}

// ---------------- final: MLP layer 2 + attention combine + output -----------
__global__ __launch_bounds__(256) void final_kernel(const float* __restrict__ w2,
                                                    const float* __restrict__ b2,
                                                    const float* __restrict__ att,
                                                    const float* __restrict__ alpha,
                                                    float* __restrict__ out) {
    __shared__ float sw2[HH * CC];
    for (int i = threadIdx.x; i < HH * CC; i += blockDim.x) sw2[i] = w2[i];
    __syncthreads();
    int idx = blockIdx.x * blockDim.x + threadIdx.x;
    if (idx >= NN * CC) return;
    int n = idx >> 4, c = idx & 15;

    float m = b2[c];
    const float4* hr = (const float4*)(g_hidden + (size_t)n * HH);
    #pragma unroll
    for (int k = 0; k < 16; k++) {
        float4 hv = hr[k];
        m = fmaf(hv.x, sw2[(4 * k + 0) * CC + c], m);
        m = fmaf(hv.y, sw2[(4 * k + 1) * CC + c], m);
        m = fmaf(hv.z, sw2[(4 * k + 2) * CC + c], m);
        m = fmaf(hv.w, sw2[(4 * k + 3) * CC + c], m);
    }

    float a0 = att[n * 2 + 0], a1 = att[n * 2 + 1];
    float mx = fmaxf(a0, a1);
    float e0 = expf(a0 - mx), e1 = expf(a1 - mx);
    float inv = 1.f / (e0 + e1);

    float sa = 1.f / (1.f + expf(-alpha[n]));
    float logits = g_hg[idx] * (e0 * inv) + g_hg[(size_t)(NN + n) * CC + c] * (e1 * inv);
    out[idx] = sa * logits + (1.f - sa) * m;
}

// ---------------- launcher ----------------
extern "C" void kernel_launch(void* const* d_in, const int* in_sizes, int n_in,
                              void* d_out, int out_size) {
    (void)in_sizes; (void)n_in; (void)out_size;
    const float* features   = (const float*)d_in[0];
    const float* label_init = (const float*)d_in[1];
    const float* one_hot    = (const float*)d_in[2];
    const float* alpha      = (const float*)d_in[3];
    const float* attention  = (const float*)d_in[4];
    const float* e_edge     = (const float*)d_in[5];
    const float* w1         = (const float*)d_in[6];
    const float* b1         = (const float*)d_in[7];
    const float* w2         = (const float*)d_in[8];
    const float* b2         = (const float*)d_in[9];
    const int*   src        = (const int*)d_in[10];
    const int*   dst        = (const int*)d_in[11];
    const int*   train      = (const int*)d_in[12];
    float*       out        = (float*)d_out;

    mask_kernel<<<(VN + 255) / 256, 256>>>(train);                                   // 1
    histconv_kernel<<<EB4 + CONVB, 256>>>(dst, w1, label_init, one_hot);             // 2
    scan_fused_kernel<<<NBLK2, 1024>>>();                                            // 3
    scatter_gemm_kernel<<<EB4 + GEMM_BLKS, 256>>>(src, dst, e_edge, features, b1);   // 4 (ncu)
    prop_kernel<0><<<PB2, 256>>>(one_hot);                                           // 5
    prop_kernel<1><<<PB2, 256>>>(one_hot);                                           // 6
    final_kernel<<<FB, 256>>>(w2, b2, attention, alpha, out);                        // 7
}

// round 12
// speedup vs baseline: 1.0513x; 1.0098x over previous
#include <cuda_runtime.h>
#include <cuda_fp16.h>
#include <math.h>

#define NN 100000
#define CC 16
#define EE 3200000
#define FF 512
#define HH 64
#define VN (2*NN)

#define NBLK2 196        // ceil(VN/1024)
#define EB4   6250       // 2*EE/(256*4)
#define PB2   25000      // VN warps / 8 warps-per-block
#define FB    6250       // NN*CC/256
#define GEMM_BLKS 782    // ceil(NN/128)
#define MASKW 3125       // NN/32
#define CONVB 3125       // conversion blocks (800000/256)

// ---------------- scratch (device globals: allocation-free) ----------------
__device__ int      g_cnt[VN];
__device__ int      g_rowptr[VN + 1];
__device__ int      g_wp[VN];
__device__ int      g_blksum[256];
__device__ int      g_arrive;
__device__ unsigned g_trainbit[MASKW];
__device__ uint2    g_edge8[2 * EE];       // {src, half2(exp(e_l0), exp(e_l1))}
__device__ uint4    g_li16[NN * 2];        // label_init fp16 (2 uint4 = 16 halves/row)
__device__ uint4    g_oh16[NN * 2];        // one_hot fp16
__device__ uint4    g_h016[VN * 2];        // layer-0 output fp16, both graphs
__device__ float    g_hg[VN * CC];         // layer-1 output fp32, both graphs
__device__ float    g_hidden[NN * HH];     // MLP hidden (relu(X@W1+b1))
__device__ __half   g_w1h[HH * FF];        // W1 transposed [n][k], fp16

// ---------------- helpers ----------------
__device__ __forceinline__ void mma_f16(float c[4], unsigned a0, unsigned a1,
                                        unsigned a2, unsigned a3,
                                        unsigned b0, unsigned b1) {
    asm volatile("mma.sync.aligned.m16n8k16.row.col.f32.f16.f16.f32 "
                 "{%0,%1,%2,%3}, {%4,%5,%6,%7}, {%8,%9}, {%0,%1,%2,%3};"
                 : "+f"(c[0]), "+f"(c[1]), "+f"(c[2]), "+f"(c[3])
                 : "r"(a0), "r"(a1), "r"(a2), "r"(a3), "r"(b0), "r"(b1));
}
__device__ __forceinline__ bool is_train(int d) {
    return (g_trainbit[d >> 5] >> (d & 31)) & 1u;
}

// ---------------- mask: train bitmask + counters reset ----------------------
__global__ __launch_bounds__(256) void mask_kernel(const int* __restrict__ train) {
    int i = blockIdx.x * blockDim.x + threadIdx.x;     // grid covers VN
    if (i < VN) g_cnt[i] = 0;
    if (i == 0) g_arrive = 0;
    if (i < MASKW) {
        unsigned m = 0;
        #pragma unroll 8
        for (int b = 0; b < 32; b++)
            m |= (train[i * 32 + b] != 0 ? 1u : 0u) << b;
        g_trainbit[i] = m;
    }
}

// ---------------- hist (bitmask) + fp16/w1 conversions, one launch ----------
__global__ __launch_bounds__(256) void histconv_kernel(const int* __restrict__ dst,
                                                       const float* __restrict__ w1,
                                                       const float* __restrict__ label_init,
                                                       const float* __restrict__ one_hot) {
    if (blockIdx.x < EB4) {
        int t = blockIdx.x * 256 + threadIdx.x;        // covers 4 edges
        int4 d4 = ((const int4*)dst)[t];
        int base = ((t << 2) >= EE) ? NN : 0;          // EE % 4 == 0
        if (!is_train(d4.x)) atomicAdd(&g_cnt[base + d4.x], 1);
        if (!is_train(d4.y)) atomicAdd(&g_cnt[base + d4.y], 1);
        if (!is_train(d4.z)) atomicAdd(&g_cnt[base + d4.z], 1);
        if (!is_train(d4.w)) atomicAdd(&g_cnt[base + d4.w], 1);
        return;
    }
    int i = (blockIdx.x - EB4) * 256 + threadIdx.x;    // < 800000
    {
        float2 li = ((const float2*)label_init)[i];
        float2 oh = ((const float2*)one_hot)[i];
        __half2 l2 = __floats2half2_rn(li.x, li.y);
        __half2 o2 = __floats2half2_rn(oh.x, oh.y);
        ((unsigned*)g_li16)[i] = *(unsigned*)&l2;
        ((unsigned*)g_oh16)[i] = *(unsigned*)&o2;
    }
    if (i < FF * HH) {
        int k = i >> 6, n = i & 63;                    // w1 is [k][n], HH=64
        g_w1h[n * FF + k] = __float2half(w1[i]);
    }
}

// ---------------- single-launch scan (grid barrier; 196 blocks all resident)
__global__ __launch_bounds__(1024) void scan_fused_kernel() {
    __shared__ int warpsum[32];
    __shared__ int s2[256];
    int b = blockIdx.x, t = threadIdx.x;
    int lane = t & 31, wid = t >> 5;
    int i = b * 1024 + t;
    int c = (i < VN) ? g_cnt[i] : 0;

    int v = c;
    #pragma unroll
    for (int off = 1; off < 32; off <<= 1) {
        int u = __shfl_up_sync(0xFFFFFFFFu, v, off);
        if (lane >= off) v += u;
    }
    if (lane == 31) warpsum[wid] = v;
    __syncthreads();
    if (wid == 0) {
        int wv = warpsum[lane];
        #pragma unroll
        for (int off = 1; off < 32; off <<= 1) {
            int u = __shfl_up_sync(0xFFFFFFFFu, wv, off);
            if (lane >= off) wv += u;
        }
        warpsum[lane] = wv;
    }
    __syncthreads();
    int incl_local = v + ((wid > 0) ? warpsum[wid - 1] : 0);
    int total = warpsum[31];

    if (t == 0) {
        g_blksum[b] = total;
        __threadfence();
        atomicAdd(&g_arrive, 1);
        while (atomicAdd(&g_arrive, 0) < NBLK2) { }
    }
    __syncthreads();

    if (t < 256) s2[t] = (t < NBLK2) ? g_blksum[t] : 0;
    __syncthreads();
    #pragma unroll
    for (int off = 1; off < 256; off <<= 1) {
        int u = 0;
        if (t < 256 && t >= off) u = s2[t - off];
        __syncthreads();
        if (t < 256) s2[t] += u;
        __syncthreads();
    }
    int prev = (b > 0) ? s2[b - 1] : 0;
    if (i < VN) {
        int incl = incl_local + prev;
        g_rowptr[i + 1] = incl;
        g_wp[i] = incl - c;
    }
    if (i == 0) g_rowptr[0] = 0;
}

// ---------------- standalone fp16 GEMM: relu(X@W1+b1) -> g_hidden -----------
__global__ __launch_bounds__(256) void gemm_kernel(const float* __restrict__ X,
                                                   const float* __restrict__ bias) {
    __shared__ __align__(16) __half Xs[128][24];   // [row][k], 48B stride
    __shared__ __align__(16) __half Ws[64][24];    // [n][k]

    int tid = threadIdx.x;
    int lane = tid & 31;
    int gid = lane >> 2, tig = lane & 3;
    int m0 = (tid >> 5) * 16;
    int n0 = blockIdx.x * 128;

    float acc[8][4];
    #pragma unroll
    for (int nt = 0; nt < 8; nt++)
        #pragma unroll
        for (int q = 0; q < 4; q++) acc[nt][q] = 0.f;

    for (int k0 = 0; k0 < FF; k0 += 16) {
        #pragma unroll
        for (int rr = 0; rr < 2; rr++) {
            int idx = tid + rr * 256;
            int row = idx >> 2, kq = idx & 3;
            int gn = n0 + row;
            float4 xv = make_float4(0.f, 0.f, 0.f, 0.f);
            if (gn < NN) xv = *(const float4*)(X + (size_t)gn * FF + k0 + kq * 4);
            __half2 h0 = __floats2half2_rn(xv.x, xv.y);
            __half2 h1 = __floats2half2_rn(xv.z, xv.w);
            *(uint2*)&Xs[row][kq * 4] = make_uint2(*(unsigned*)&h0, *(unsigned*)&h1);
        }
        if (tid < 128) {
            int row = tid >> 1, part = tid & 1;
            uint4 wv = *(const uint4*)(g_w1h + (size_t)row * FF + k0 + part * 8);
            *(uint4*)&Ws[row][part * 8] = wv;
        }
        __syncthreads();
        unsigned a0 = *(unsigned*)&Xs[m0 + gid    ][2 * tig    ];
        unsigned a1 = *(unsigned*)&Xs[m0 + gid + 8][2 * tig    ];
        unsigned a2 = *(unsigned*)&Xs[m0 + gid    ][2 * tig + 8];
        unsigned a3 = *(unsigned*)&Xs[m0 + gid + 8][2 * tig + 8];
        #pragma unroll
        for (int nt = 0; nt < 8; nt++) {
            unsigned b0 = *(unsigned*)&Ws[nt * 8 + gid][2 * tig    ];
            unsigned b1 = *(unsigned*)&Ws[nt * 8 + gid][2 * tig + 8];
            mma_f16(acc[nt], a0, a1, a2, a3, b0, b1);
        }
        __syncthreads();
    }

    #pragma unroll
    for (int rr = 0; rr < 2; rr++) {
        int row = n0 + m0 + rr * 8 + gid;
        if (row >= NN) continue;
        #pragma unroll
        for (int nt = 0; nt < 8; nt++) {
            int col = nt * 8 + 2 * tig;
            float v0 = fmaxf(acc[nt][rr * 2 + 0] + bias[col], 0.f);
            float v1 = fmaxf(acc[nt][rr * 2 + 1] + bias[col + 1], 0.f);
            *(float2*)(g_hidden + (size_t)row * HH + col) = make_float2(v0, v1);
        }
    }
}

// ---------------- standalone CSR scatter (30 regs, 86% occ — measured) ------
__global__ __launch_bounds__(256) void scatter_kernel(
        const int* __restrict__ src, const int* __restrict__ dst,
        const float* __restrict__ e_edge) {
    int t = blockIdx.x * 256 + threadIdx.x;            // covers 4 edges
    int4   s4 = ((const int4*)src)[t];
    int4   d4 = ((const int4*)dst)[t];
    float4 e0 = ((const float4*)e_edge)[t];
    float4 e1 = ((const float4*)(e_edge + 2 * (size_t)EE))[t];
    int base = ((t << 2) >= EE) ? NN : 0;
    // softmax max-shift cancels; exp(|e|<6) safe; fp16 range ok (exp<=e^6~403)
    if (!is_train(d4.x)) {
        int p = atomicAdd(&g_wp[base + d4.x], 1);
        __half2 w = __floats2half2_rn(__expf(e0.x), __expf(e1.x));
        g_edge8[p] = make_uint2((unsigned)s4.x, *(unsigned*)&w);
    }
    if (!is_train(d4.y)) {
        int p = atomicAdd(&g_wp[base + d4.y], 1);
        __half2 w = __floats2half2_rn(__expf(e0.y), __expf(e1.y));
        g_edge8[p] = make_uint2((unsigned)s4.y, *(unsigned*)&w);
    }
    if (!is_train(d4.z)) {
        int p = atomicAdd(&g_wp[base + d4.z], 1);
        __half2 w = __floats2half2_rn(__expf(e0.z), __expf(e1.z));
        g_edge8[p] = make_uint2((unsigned)s4.z, *(unsigned*)&w);
    }
    if (!is_train(d4.w)) {
        int p = atomicAdd(&g_wp[base + d4.w], 1);
        __half2 w = __floats2half2_rn(__expf(e0.w), __expf(e1.w));
        g_edge8[p] = make_uint2((unsigned)s4.w, *(unsigned*)&w);
    }
}

// ---- propagate (gather, warp-per-vnode, 2 lanes/edge, dual-edge MLP) -------
template <int LAYER>
__global__ __launch_bounds__(256) void prop_kernel(const float* __restrict__ one_hot) {
    int v    = (blockIdx.x * blockDim.x + threadIdx.x) >> 5;
    int lane = threadIdx.x & 31;
    if (v >= VN) return;
    int n = (v < NN) ? v : v - NN;

    if (is_train(n)) {
        if (LAYER == 0) {
            if (lane < 2) g_h016[(size_t)v * 2 + lane] = g_oh16[(size_t)n * 2 + lane];
        } else {
            if (lane < CC) g_hg[(size_t)v * CC + lane] = one_hot[(size_t)n * CC + lane];
        }
        return;
    }

    const uint4* hbase = (LAYER == 0) ? g_li16
                                      : (g_h016 + ((v < NN) ? 0 : (size_t)NN * 2));
    int beg = g_rowptr[v], end = g_rowptr[v + 1];
    int half = lane & 1;

    float a[8];
    #pragma unroll
    for (int q = 0; q < 8; q++) a[q] = 0.f;
    float sw = 0.f;

    for (int j = beg + (lane >> 1); j < end; j += 32) {
        uint2 r1 = g_edge8[j];
        int j2 = j + 16;
        uint2 r2 = (j2 < end) ? g_edge8[j2] : make_uint2(r1.x, 0u);  // w=0 pad
        int s1 = (int)r1.x, s2 = (int)r2.x;
        __half2 wh1 = *(__half2*)&r1.y, wh2 = *(__half2*)&r2.y;
        float w1 = (LAYER == 0) ? __low2float(wh1) : __high2float(wh1);
        float w2 = (LAYER == 0) ? __low2float(wh2) : __high2float(wh2);
        uint4 u1 = hbase[(size_t)s1 * 2 + half];
        uint4 u2 = hbase[(size_t)s2 * 2 + half];
        {
            float2 f0 = __half22float2(*(__half2*)&u1.x);
            float2 f1 = __half22float2(*(__half2*)&u1.y);
            float2 f2 = __half22float2(*(__half2*)&u1.z);
            float2 f3 = __half22float2(*(__half2*)&u1.w);
            a[0] = fmaf(w1, f0.x, a[0]); a[1] = fmaf(w1, f0.y, a[1]);
            a[2] = fmaf(w1, f1.x, a[2]); a[3] = fmaf(w1, f1.y, a[3]);
            a[4] = fmaf(w1, f2.x, a[4]); a[5] = fmaf(w1, f2.y, a[5]);
            a[6] = fmaf(w1, f3.x, a[6]); a[7] = fmaf(w1, f3.y, a[7]);
        }
        {
            float2 f0 = __half22float2(*(__half2*)&u2.x);
            float2 f1 = __half22float2(*(__half2*)&u2.y);
            float2 f2 = __half22float2(*(__half2*)&u2.z);
            float2 f3 = __half22float2(*(__half2*)&u2.w);
            a[0] = fmaf(w2, f0.x, a[0]); a[1] = fmaf(w2, f0.y, a[1]);
            a[2] = fmaf(w2, f1.x, a[2]); a[3] = fmaf(w2, f1.y, a[3]);
            a[4] = fmaf(w2, f2.x, a[4]); a[5] = fmaf(w2, f2.y, a[5]);
            a[6] = fmaf(w2, f3.x, a[6]); a[7] = fmaf(w2, f3.y, a[7]);
        }
        sw += w1 + w2;
    }
    #pragma unroll
    for (int off = 2; off < 32; off <<= 1) {
        #pragma unroll
        for (int q = 0; q < 8; q++)
            a[q] += __shfl_xor_sync(0xFFFFFFFFu, a[q], off);
        sw += __shfl_xor_sync(0xFFFFFFFFu, sw, off);
    }
    if (lane < 2) {
        float inv = (sw > 0.f) ? (1.f / sw) : 0.f;
        #pragma unroll
        for (int q = 0; q < 8; q++) a[q] *= inv;
        if (LAYER == 0) {
            __half2 o0 = __floats2half2_rn(a[0], a[1]);
            __half2 o1 = __floats2half2_rn(a[2], a[3]);
            __half2 o2 = __floats2half2_rn(a[4], a[5]);
            __half2 o3 = __floats2half2_rn(a[6], a[7]);
            uint4 u;
            u.x = *(unsigned*)&o0; u.y = *(unsigned*)&o1;
            u.z = *(unsigned*)&o2; u.w = *(unsigned*)&o3;
            g_h016[(size_t)v * 2 + half] = u;
        } else {
            float* op = g_hg + (size_t)v * CC + half * 8;
            ((float4*)op)[0] = make_float4(a[0], a[1], a[2], a[3]);
            ((float4*)op)[1] = make_float4(a[4], a[5], a[6], a[7]);
        }
    }
}

// ---------------- final: MLP layer 2 + attention combine + output -----------
__global__ __launch_bounds__(256) void final_kernel(const float* __restrict__ w2,
                                                    const float* __restrict__ b2,
                                                    const float* __restrict__ att,
                                                    const float* __restrict__ alpha,
                                                    float* __restrict__ out) {
    __shared__ float sw2[HH * CC];
    for (int i = threadIdx.x; i < HH * CC; i += blockDim.x) sw2[i] = w2[i];
    __syncthreads();
    int idx = blockIdx.x * blockDim.x + threadIdx.x;
    if (idx >= NN * CC) return;
    int n = idx >> 4, c = idx & 15;

    float m = b2[c];
    const float4* hr = (const float4*)(g_hidden + (size_t)n * HH);
    #pragma unroll
    for (int k = 0; k < 16; k++) {
        float4 hv = hr[k];
        m = fmaf(hv.x, sw2[(4 * k + 0) * CC + c], m);
        m = fmaf(hv.y, sw2[(4 * k + 1) * CC + c], m);
        m = fmaf(hv.z, sw2[(4 * k + 2) * CC + c], m);
        m = fmaf(hv.w, sw2[(4 * k + 3) * CC + c], m);
    }

    float a0 = att[n * 2 + 0], a1 = att[n * 2 + 1];
    float mx = fmaxf(a0, a1);
    float e0 = expf(a0 - mx), e1 = expf(a1 - mx);
    float inv = 1.f / (e0 + e1);

    float sa = 1.f / (1.f + expf(-alpha[n]));
    float logits = g_hg[idx] * (e0 * inv) + g_hg[(size_t)(NN + n) * CC + c] * (e1 * inv);
    out[idx] = sa * logits + (1.f - sa) * m;
}

// ---------------- launcher ----------------
extern "C" void kernel_launch(void* const* d_in, const int* in_sizes, int n_in,
                              void* d_out, int out_size) {
    (void)in_sizes; (void)n_in; (void)out_size;
    const float* features   = (const float*)d_in[0];
    const float* label_init = (const float*)d_in[1];
    const float* one_hot    = (const float*)d_in[2];
    const float* alpha      = (const float*)d_in[3];
    const float* attention  = (const float*)d_in[4];
    const float* e_edge     = (const float*)d_in[5];
    const float* w1         = (const float*)d_in[6];
    const float* b1         = (const float*)d_in[7];
    const float* w2         = (const float*)d_in[8];
    const float* b2         = (const float*)d_in[9];
    const int*   src        = (const int*)d_in[10];
    const int*   dst        = (const int*)d_in[11];
    const int*   train      = (const int*)d_in[12];
    float*       out        = (float*)d_out;

    mask_kernel<<<(VN + 255) / 256, 256>>>(train);                          // 1
    histconv_kernel<<<EB4 + CONVB, 256>>>(dst, w1, label_init, one_hot);    // 2
    scan_fused_kernel<<<NBLK2, 1024>>>();                                   // 3
    gemm_kernel<<<GEMM_BLKS, 256>>>(features, b1);                          // 4 (ncu)
    scatter_kernel<<<EB4, 256>>>(src, dst, e_edge);                         // 5
    prop_kernel<0><<<PB2, 256>>>(one_hot);                                  // 6
    prop_kernel<1><<<PB2, 256>>>(one_hot);                                  // 7
    final_kernel<<<FB, 256>>>(w2, b2, attention, alpha, out);               // 8
}

// round 13
// speedup vs baseline: 1.0949x; 1.0415x over previous
#include <cuda_runtime.h>
#include <cuda_fp16.h>
#include <math.h>

#define NN 100000
#define CC 16
#define EE 3200000
#define FF 512
#define HH 64
#define VN (2*NN)

#define NBLK2 196        // ceil(VN/1024)
#define EB4   6250       // 2*EE/(256*4)
#define PB2   25000      // VN warps / 8 warps-per-block
#define FB    6250       // NN*CC/256
#define GEMM_BLKS 782    // ceil(NN/128)
#define MASKW 3125       // NN/32
#define CONVB 3125       // conversion blocks (800000/256)
#define NTILES 32        // FF/16

// ---------------- scratch (device globals: allocation-free) ----------------
__device__ int      g_cnt[VN];
__device__ int      g_rowptr[VN + 1];
__device__ int      g_wp[VN];
__device__ int      g_blksum[256];
__device__ int      g_arrive;
__device__ unsigned g_trainbit[MASKW];
__device__ uint2    g_edge8[2 * EE];       // {src, half2(exp(e_l0), exp(e_l1))}
__device__ uint4    g_li16[NN * 2];        // label_init fp16 (2 uint4 = 16 halves/row)
__device__ uint4    g_oh16[NN * 2];        // one_hot fp16
__device__ uint4    g_h016[VN * 2];        // layer-0 output fp16, both graphs
__device__ float    g_hg[VN * CC];         // layer-1 output fp32, both graphs
__device__ float    g_hidden[NN * HH];     // MLP hidden (relu(X@W1+b1))
__device__ float    g_w1t[FF * HH];        // tf32-rounded W1, [k][n]

// ---------------- helpers ----------------
__device__ __forceinline__ unsigned f2tf32(float x) {
    unsigned r;
    asm("cvt.rna.tf32.f32 %0, %1;" : "=r"(r) : "f"(x));
    return r;
}
__device__ __forceinline__ void mma_tf32(float c[4], const unsigned a[4],
                                         unsigned b0, unsigned b1) {
    asm volatile("mma.sync.aligned.m16n8k8.row.col.f32.tf32.tf32.f32 "
                 "{%0,%1,%2,%3}, {%4,%5,%6,%7}, {%8,%9}, {%0,%1,%2,%3};"
                 : "+f"(c[0]), "+f"(c[1]), "+f"(c[2]), "+f"(c[3])
                 : "r"(a[0]), "r"(a[1]), "r"(a[2]), "r"(a[3]), "r"(b0), "r"(b1));
}
__device__ __forceinline__ void cp_async16(void* smem, const void* gmem, int sz) {
    unsigned saddr = (unsigned)__cvta_generic_to_shared(smem);
    asm volatile("cp.async.cg.shared.global [%0], [%1], 16, %2;"
                 :: "r"(saddr), "l"(gmem), "r"(sz));
}
__device__ __forceinline__ bool is_train(int d) {
    return (g_trainbit[d >> 5] >> (d & 31)) & 1u;
}

// ---------------- mask: train bitmask + counters reset ----------------------
__global__ __launch_bounds__(256) void mask_kernel(const int* __restrict__ train) {
    int i = blockIdx.x * blockDim.x + threadIdx.x;     // grid covers VN
    if (i < VN) g_cnt[i] = 0;
    if (i == 0) g_arrive = 0;
    if (i < MASKW) {
        unsigned m = 0;
        #pragma unroll 8
        for (int b = 0; b < 32; b++)
            m |= (train[i * 32 + b] != 0 ? 1u : 0u) << b;
        g_trainbit[i] = m;
    }
}

// ---------------- hist (bitmask) + fp16/w1 conversions, one launch ----------
__global__ __launch_bounds__(256) void histconv_kernel(const int* __restrict__ dst,
                                                       const float* __restrict__ w1,
                                                       const float* __restrict__ label_init,
                                                       const float* __restrict__ one_hot) {
    if (blockIdx.x < EB4) {
        int t = blockIdx.x * 256 + threadIdx.x;        // covers 4 edges
        int4 d4 = ((const int4*)dst)[t];
        int base = ((t << 2) >= EE) ? NN : 0;          // EE % 4 == 0
        if (!is_train(d4.x)) atomicAdd(&g_cnt[base + d4.x], 1);
        if (!is_train(d4.y)) atomicAdd(&g_cnt[base + d4.y], 1);
        if (!is_train(d4.z)) atomicAdd(&g_cnt[base + d4.z], 1);
        if (!is_train(d4.w)) atomicAdd(&g_cnt[base + d4.w], 1);
        return;
    }
    int i = (blockIdx.x - EB4) * 256 + threadIdx.x;    // < 800000
    {
        float2 li = ((const float2*)label_init)[i];
        float2 oh = ((const float2*)one_hot)[i];
        __half2 l2 = __floats2half2_rn(li.x, li.y);
        __half2 o2 = __floats2half2_rn(oh.x, oh.y);
        ((unsigned*)g_li16)[i] = *(unsigned*)&l2;
        ((unsigned*)g_oh16)[i] = *(unsigned*)&o2;
    }
    if (i < FF * HH) g_w1t[i] = __uint_as_float(f2tf32(w1[i]));  // [k][n] layout
}

// ---------------- single-launch scan (grid barrier; 196 blocks all resident)
__global__ __launch_bounds__(1024) void scan_fused_kernel() {
    __shared__ int warpsum[32];
    __shared__ int s2[256];
    int b = blockIdx.x, t = threadIdx.x;
    int lane = t & 31, wid = t >> 5;
    int i = b * 1024 + t;
    int c = (i < VN) ? g_cnt[i] : 0;

    int v = c;
    #pragma unroll
    for (int off = 1; off < 32; off <<= 1) {
        int u = __shfl_up_sync(0xFFFFFFFFu, v, off);
        if (lane >= off) v += u;
    }
    if (lane == 31) warpsum[wid] = v;
    __syncthreads();
    if (wid == 0) {
        int wv = warpsum[lane];
        #pragma unroll
        for (int off = 1; off < 32; off <<= 1) {
            int u = __shfl_up_sync(0xFFFFFFFFu, wv, off);
            if (lane >= off) wv += u;
        }
        warpsum[lane] = wv;
    }
    __syncthreads();
    int incl_local = v + ((wid > 0) ? warpsum[wid - 1] : 0);
    int total = warpsum[31];

    if (t == 0) {
        g_blksum[b] = total;
        __threadfence();
        atomicAdd(&g_arrive, 1);
        while (atomicAdd(&g_arrive, 0) < NBLK2) { }
    }
    __syncthreads();

    if (t < 256) s2[t] = (t < NBLK2) ? g_blksum[t] : 0;
    __syncthreads();
    #pragma unroll
    for (int off = 1; off < 256; off <<= 1) {
        int u = 0;
        if (t < 256 && t >= off) u = s2[t - off];
        __syncthreads();
        if (t < 256) s2[t] += u;
        __syncthreads();
    }
    int prev = (b > 0) ? s2[b - 1] : 0;
    if (i < VN) {
        int incl = incl_local + prev;
        g_rowptr[i + 1] = incl;
        g_wp[i] = incl - c;
    }
    if (i == 0) g_rowptr[0] = 0;
}

// ------- standalone tf32 GEMM, 3-stage cp.async pipeline --------------------
// relu(X[N,512] @ W1t[512,64] + b1) -> g_hidden
// Xs stride 20 floats: tf32 A-frag LDS.32 conflict-free (20 mod 32 partitions banks).
// Ws stride 72 floats: B-frag rows land on disjoint bank groups (72 mod 32 = 8).
__global__ __launch_bounds__(256) void gemm_kernel(const float* __restrict__ X,
                                                   const float* __restrict__ bias) {
    __shared__ __align__(16) float Xs[3][128][20];
    __shared__ __align__(16) float Ws[3][16][72];

    int tid = threadIdx.x;
    int lane = tid & 31;
    int gid = lane >> 2, tig = lane & 3;
    int m0 = (tid >> 5) * 16;
    int n0 = blockIdx.x * 128;

    // staging roles (X: 2 chunks/thread; W: 1 chunk/thread)
    int xr0 = tid >> 2,          xs0 = tid & 3;          // chunk = tid
    int xr1 = (tid + 256) >> 2,  xs1 = xs0;              // chunk = tid + 256
    int wk  = tid >> 4,          ws  = tid & 15;

    float acc[8][4];
    #pragma unroll
    for (int nt = 0; nt < 8; nt++)
        #pragma unroll
        for (int q = 0; q < 4; q++) acc[nt][q] = 0.f;

    int gn0 = n0 + xr0, gn1 = n0 + xr1;
    const float* xsrc0 = X + (size_t)((gn0 < NN) ? gn0 : 0) * FF + xs0 * 4;
    const float* xsrc1 = X + (size_t)((gn1 < NN) ? gn1 : 0) * FF + xs1 * 4;
    int sz0 = (gn0 < NN) ? 16 : 0;
    int sz1 = (gn1 < NN) ? 16 : 0;
    const float* wsrc = g_w1t + wk * HH + ws * 4;

    // prologue: stage tiles 0 and 1
    #pragma unroll
    for (int p = 0; p < 2; p++) {
        int k0 = p * 16;
        cp_async16(&Xs[p][xr0][xs0 * 4], xsrc0 + k0, sz0);
        cp_async16(&Xs[p][xr1][xs1 * 4], xsrc1 + k0, sz1);
        cp_async16(&Ws[p][wk][ws * 4], wsrc + (size_t)k0 * HH, 16);
        asm volatile("cp.async.commit_group;");
    }

    #pragma unroll 1
    for (int t = 0; t < NTILES; t++) {
        int s = t % 3;
        asm volatile("cp.async.wait_group 1;");
        __syncthreads();
        if (t + 2 < NTILES) {
            int sn = (t + 2) % 3;
            int k0 = (t + 2) * 16;
            cp_async16(&Xs[sn][xr0][xs0 * 4], xsrc0 + k0, sz0);
            cp_async16(&Xs[sn][xr1][xs1 * 4], xsrc1 + k0, sz1);
            cp_async16(&Ws[sn][wk][ws * 4], wsrc + (size_t)k0 * HH, 16);
        }
        asm volatile("cp.async.commit_group;");

        #pragma unroll
        for (int ks = 0; ks < 2; ks++) {
            unsigned a[4];
            a[0] = f2tf32(Xs[s][m0 + gid    ][ks * 8 + tig    ]);
            a[1] = f2tf32(Xs[s][m0 + gid + 8][ks * 8 + tig    ]);
            a[2] = f2tf32(Xs[s][m0 + gid    ][ks * 8 + tig + 4]);
            a[3] = f2tf32(Xs[s][m0 + gid + 8][ks * 8 + tig + 4]);
            #pragma unroll
            for (int nt = 0; nt < 8; nt++) {
                unsigned b0 = __float_as_uint(Ws[s][ks * 8 + tig    ][nt * 8 + gid]);
                unsigned b1 = __float_as_uint(Ws[s][ks * 8 + tig + 4][nt * 8 + gid]);
                mma_tf32(acc[nt], a, b0, b1);
            }
        }
    }

    // epilogue: bias + relu -> g_hidden
    #pragma unroll
    for (int rr = 0; rr < 2; rr++) {
        int row = n0 + m0 + rr * 8 + gid;
        if (row >= NN) continue;
        #pragma unroll
        for (int nt = 0; nt < 8; nt++) {
            int col = nt * 8 + 2 * tig;
            float v0 = fmaxf(acc[nt][rr * 2 + 0] + bias[col], 0.f);
            float v1 = fmaxf(acc[nt][rr * 2 + 1] + bias[col + 1], 0.f);
            *(float2*)(g_hidden + (size_t)row * HH + col) = make_float2(v0, v1);
        }
    }
}

// ---------------- standalone CSR scatter (30 regs, 86% occ — measured) ------
__global__ __launch_bounds__(256) void scatter_kernel(
        const int* __restrict__ src, const int* __restrict__ dst,
        const float* __restrict__ e_edge) {
    int t = blockIdx.x * 256 + threadIdx.x;            // covers 4 edges
    int4   s4 = ((const int4*)src)[t];
    int4   d4 = ((const int4*)dst)[t];
    float4 e0 = ((const float4*)e_edge)[t];
    float4 e1 = ((const float4*)(e_edge + 2 * (size_t)EE))[t];
    int base = ((t << 2) >= EE) ? NN : 0;
    // softmax max-shift cancels; exp(|e|<6) safe; fp16 range ok (exp<=e^6~403)
    if (!is_train(d4.x)) {
        int p = atomicAdd(&g_wp[base + d4.x], 1);
        __half2 w = __floats2half2_rn(__expf(e0.x), __expf(e1.x));
        g_edge8[p] = make_uint2((unsigned)s4.x, *(unsigned*)&w);
    }
    if (!is_train(d4.y)) {
        int p = atomicAdd(&g_wp[base + d4.y], 1);
        __half2 w = __floats2half2_rn(__expf(e0.y), __expf(e1.y));
        g_edge8[p] = make_uint2((unsigned)s4.y, *(unsigned*)&w);
    }
    if (!is_train(d4.z)) {
        int p = atomicAdd(&g_wp[base + d4.z], 1);
        __half2 w = __floats2half2_rn(__expf(e0.z), __expf(e1.z));
        g_edge8[p] = make_uint2((unsigned)s4.z, *(unsigned*)&w);
    }
    if (!is_train(d4.w)) {
        int p = atomicAdd(&g_wp[base + d4.w], 1);
        __half2 w = __floats2half2_rn(__expf(e0.w), __expf(e1.w));
        g_edge8[p] = make_uint2((unsigned)s4.w, *(unsigned*)&w);
    }
}

// ---- propagate (gather, warp-per-vnode, 2 lanes/edge, dual-edge MLP) -------
template <int LAYER>
__global__ __launch_bounds__(256) void prop_kernel(const float* __restrict__ one_hot) {
    int v    = (blockIdx.x * blockDim.x + threadIdx.x) >> 5;
    int lane = threadIdx.x & 31;
    if (v >= VN) return;
    int n = (v < NN) ? v : v - NN;

    if (is_train(n)) {
        if (LAYER == 0) {
            if (lane < 2) g_h016[(size_t)v * 2 + lane] = g_oh16[(size_t)n * 2 + lane];
        } else {
            if (lane < CC) g_hg[(size_t)v * CC + lane] = one_hot[(size_t)n * CC + lane];
        }
        return;
    }

    const uint4* hbase = (LAYER == 0) ? g_li16
                                      : (g_h016 + ((v < NN) ? 0 : (size_t)NN * 2));
    int beg = g_rowptr[v], end = g_rowptr[v + 1];
    int half = lane & 1;

    float a[8];
    #pragma unroll
    for (int q = 0; q < 8; q++) a[q] = 0.f;
    float sw = 0.f;

    for (int j = beg + (lane >> 1); j < end; j += 32) {
        uint2 r1 = g_edge8[j];
        int j2 = j + 16;
        uint2 r2 = (j2 < end) ? g_edge8[j2] : make_uint2(r1.x, 0u);  // w=0 pad
        int s1 = (int)r1.x, s2 = (int)r2.x;
        __half2 wh1 = *(__half2*)&r1.y, wh2 = *(__half2*)&r2.y;
        float w1 = (LAYER == 0) ? __low2float(wh1) : __high2float(wh1);
        float w2 = (LAYER == 0) ? __low2float(wh2) : __high2float(wh2);
        uint4 u1 = hbase[(size_t)s1 * 2 + half];
        uint4 u2 = hbase[(size_t)s2 * 2 + half];
        {
            float2 f0 = __half22float2(*(__half2*)&u1.x);
            float2 f1 = __half22float2(*(__half2*)&u1.y);
            float2 f2 = __half22float2(*(__half2*)&u1.z);
            float2 f3 = __half22float2(*(__half2*)&u1.w);
            a[0] = fmaf(w1, f0.x, a[0]); a[1] = fmaf(w1, f0.y, a[1]);
            a[2] = fmaf(w1, f1.x, a[2]); a[3] = fmaf(w1, f1.y, a[3]);
            a[4] = fmaf(w1, f2.x, a[4]); a[5] = fmaf(w1, f2.y, a[5]);
            a[6] = fmaf(w1, f3.x, a[6]); a[7] = fmaf(w1, f3.y, a[7]);
        }
        {
            float2 f0 = __half22float2(*(__half2*)&u2.x);
            float2 f1 = __half22float2(*(__half2*)&u2.y);
            float2 f2 = __half22float2(*(__half2*)&u2.z);
            float2 f3 = __half22float2(*(__half2*)&u2.w);
            a[0] = fmaf(w2, f0.x, a[0]); a[1] = fmaf(w2, f0.y, a[1]);
            a[2] = fmaf(w2, f1.x, a[2]); a[3] = fmaf(w2, f1.y, a[3]);
            a[4] = fmaf(w2, f2.x, a[4]); a[5] = fmaf(w2, f2.y, a[5]);
            a[6] = fmaf(w2, f3.x, a[6]); a[7] = fmaf(w2, f3.y, a[7]);
        }
        sw += w1 + w2;
    }
    #pragma unroll
    for (int off = 2; off < 32; off <<= 1) {
        #pragma unroll
        for (int q = 0; q < 8; q++)
            a[q] += __shfl_xor_sync(0xFFFFFFFFu, a[q], off);
        sw += __shfl_xor_sync(0xFFFFFFFFu, sw, off);
    }
    if (lane < 2) {
        float inv = (sw > 0.f) ? (1.f / sw) : 0.f;
        #pragma unroll
        for (int q = 0; q < 8; q++) a[q] *= inv;
        if (LAYER == 0) {
            __half2 o0 = __floats2half2_rn(a[0], a[1]);
            __half2 o1 = __floats2half2_rn(a[2], a[3]);
            __half2 o2 = __floats2half2_rn(a[4], a[5]);
            __half2 o3 = __floats2half2_rn(a[6], a[7]);
            uint4 u;
            u.x = *(unsigned*)&o0; u.y = *(unsigned*)&o1;
            u.z = *(unsigned*)&o2; u.w = *(unsigned*)&o3;
            g_h016[(size_t)v * 2 + half] = u;
        } else {
            float* op = g_hg + (size_t)v * CC + half * 8;
            ((float4*)op)[0] = make_float4(a[0], a[1], a[2], a[3]);
            ((float4*)op)[1] = make_float4(a[4], a[5], a[6], a[7]);
        }
    }
}

// ---------------- final: MLP layer 2 + attention combine + output -----------
__global__ __launch_bounds__(256) void final_kernel(const float* __restrict__ w2,
                                                    const float* __restrict__ b2,
                                                    const float* __restrict__ att,
                                                    const float* __restrict__ alpha,
                                                    float* __restrict__ out) {
    __shared__ float sw2[HH * CC];
    for (int i = threadIdx.x; i < HH * CC; i += blockDim.x) sw2[i] = w2[i];
    __syncthreads();
    int idx = blockIdx.x * blockDim.x + threadIdx.x;
    if (idx >= NN * CC) return;
    int n = idx >> 4, c = idx & 15;

    float m = b2[c];
    const float4* hr = (const float4*)(g_hidden + (size_t)n * HH);
    #pragma unroll
    for (int k = 0; k < 16; k++) {
        float4 hv = hr[k];
        m = fmaf(hv.x, sw2[(4 * k + 0) * CC + c], m);
        m = fmaf(hv.y, sw2[(4 * k + 1) * CC + c], m);
        m = fmaf(hv.z, sw2[(4 * k + 2) * CC + c], m);
        m = fmaf(hv.w, sw2[(4 * k + 3) * CC + c], m);
    }

    float a0 = att[n * 2 + 0], a1 = att[n * 2 + 1];
    float mx = fmaxf(a0, a1);
    float e0 = expf(a0 - mx), e1 = expf(a1 - mx);
    float inv = 1.f / (e0 + e1);

    float sa = 1.f / (1.f + expf(-alpha[n]));
    float logits = g_hg[idx] * (e0 * inv) + g_hg[(size_t)(NN + n) * CC + c] * (e1 * inv);
    out[idx] = sa * logits + (1.f - sa) * m;
}

// ---------------- launcher ----------------
extern "C" void kernel_launch(void* const* d_in, const int* in_sizes, int n_in,
                              void* d_out, int out_size) {
    (void)in_sizes; (void)n_in; (void)out_size;
    const float* features   = (const float*)d_in[0];
    const float* label_init = (const float*)d_in[1];
    const float* one_hot    = (const float*)d_in[2];
    const float* alpha      = (const float*)d_in[3];
    const float* attention  = (const float*)d_in[4];
    const float* e_edge     = (const float*)d_in[5];
    const float* w1         = (const float*)d_in[6];
    const float* b1         = (const float*)d_in[7];
    const float* w2         = (const float*)d_in[8];
    const float* b2         = (const float*)d_in[9];
    const int*   src        = (const int*)d_in[10];
    const int*   dst        = (const int*)d_in[11];
    const int*   train      = (const int*)d_in[12];
    float*       out        = (float*)d_out;

    mask_kernel<<<(VN + 255) / 256, 256>>>(train);                          // 1
    histconv_kernel<<<EB4 + CONVB, 256>>>(dst, w1, label_init, one_hot);    // 2
    scan_fused_kernel<<<NBLK2, 1024>>>();                                   // 3
    gemm_kernel<<<GEMM_BLKS, 256>>>(features, b1);                          // 4 (ncu)
    scatter_kernel<<<EB4, 256>>>(src, dst, e_edge);                         // 5
    prop_kernel<0><<<PB2, 256>>>(one_hot);                                  // 6
    prop_kernel<1><<<PB2, 256>>>(one_hot);                                  // 7
    final_kernel<<<FB, 256>>>(w2, b2, attention, alpha, out);               // 8
}

// round 14
// speedup vs baseline: 1.1919x; 1.0885x over previous
#include <cuda_runtime.h>
#include <cuda_fp16.h>
#include <math.h>

#define NN 100000
#define CC 16
#define EE 3200000
#define FF 512
#define HH 64
#define VN (2*NN)

#define NBLK2 196        // ceil(VN/1024)
#define EB4   6250       // 2*EE/(256*4)
#define PB2   25000      // VN warps / 8 warps-per-block
#define FB    6250       // NN*CC/256
#define GEMM_BLKS 782    // ceil(NN/128)
#define MASKW 3125       // NN/32
#define CONVB 3125       // prep blocks (800000/256)
#define NTILES 32        // FF/16

// ---------------- scratch (device globals: allocation-free) ----------------
__device__ int      g_cnt[VN];
__device__ int      g_rowptr[VN + 1];
__device__ int      g_wp[VN];
__device__ int      g_blksum[256];
__device__ int      g_arrive;
__device__ unsigned g_trainbit[MASKW];
__device__ uint2    g_edge8[2 * EE];       // {src, half2(exp(e_l0), exp(e_l1))}
__device__ uint4    g_li16[NN * 2];        // label_init fp16 (2 uint4 = 16 halves/row)
__device__ uint4    g_oh16[NN * 2];        // one_hot fp16
__device__ uint4    g_h016[VN * 2];        // layer-0 output fp16, both graphs
__device__ float    g_hg[VN * CC];         // layer-1 output fp32, both graphs
__device__ float    g_hidden[NN * HH];     // MLP hidden (relu(X@W1+b1))
__device__ float    g_w1t[FF * HH];        // tf32-rounded W1, [k][n]

// ---------------- helpers ----------------
__device__ __forceinline__ unsigned f2tf32(float x) {
    unsigned r;
    asm("cvt.rna.tf32.f32 %0, %1;" : "=r"(r) : "f"(x));
    return r;
}
__device__ __forceinline__ void mma_tf32(float c[4], const unsigned a[4],
                                         unsigned b0, unsigned b1) {
    asm volatile("mma.sync.aligned.m16n8k8.row.col.f32.tf32.tf32.f32 "
                 "{%0,%1,%2,%3}, {%4,%5,%6,%7}, {%8,%9}, {%0,%1,%2,%3};"
                 : "+f"(c[0]), "+f"(c[1]), "+f"(c[2]), "+f"(c[3])
                 : "r"(a[0]), "r"(a[1]), "r"(a[2]), "r"(a[3]), "r"(b0), "r"(b1));
}
__device__ __forceinline__ void cp_async16(void* smem, const void* gmem, int sz) {
    unsigned saddr = (unsigned)__cvta_generic_to_shared(smem);
    asm volatile("cp.async.cg.shared.global [%0], [%1], 16, %2;"
                 :: "r"(saddr), "l"(gmem), "r"(sz));
}
__device__ __forceinline__ bool is_train(int d) {
    return (g_trainbit[d >> 5] >> (d & 31)) & 1u;
}

// ------- prep: bitmask + counters + w1 tf32 + fp16 conversions (fork point) -
__global__ __launch_bounds__(256) void prep_kernel(const int* __restrict__ train,
                                                   const float* __restrict__ w1,
                                                   const float* __restrict__ label_init,
                                                   const float* __restrict__ one_hot) {
    int i = blockIdx.x * blockDim.x + threadIdx.x;     // covers 800000
    if (i < NN * CC / 2) {
        float2 li = ((const float2*)label_init)[i];
        float2 oh = ((const float2*)one_hot)[i];
        __half2 l2 = __floats2half2_rn(li.x, li.y);
        __half2 o2 = __floats2half2_rn(oh.x, oh.y);
        ((unsigned*)g_li16)[i] = *(unsigned*)&l2;
        ((unsigned*)g_oh16)[i] = *(unsigned*)&o2;
    }
    if (i < FF * HH) g_w1t[i] = __uint_as_float(f2tf32(w1[i]));
    if (i < VN) g_cnt[i] = 0;
    if (i == 0) g_arrive = 0;
    if (i < MASKW) {
        unsigned m = 0;
        #pragma unroll 8
        for (int b = 0; b < 32; b++)
            m |= (train[i * 32 + b] != 0 ? 1u : 0u) << b;
        g_trainbit[i] = m;
    }
}

// ---------------- hist (bitmask + int4 vectorized) --------------------------
__global__ __launch_bounds__(256) void hist_kernel(const int* __restrict__ dst) {
    int t = blockIdx.x * 256 + threadIdx.x;            // covers 4 edges
    int4 d4 = ((const int4*)dst)[t];
    int base = ((t << 2) >= EE) ? NN : 0;              // EE % 4 == 0
    if (!is_train(d4.x)) atomicAdd(&g_cnt[base + d4.x], 1);
    if (!is_train(d4.y)) atomicAdd(&g_cnt[base + d4.y], 1);
    if (!is_train(d4.z)) atomicAdd(&g_cnt[base + d4.z], 1);
    if (!is_train(d4.w)) atomicAdd(&g_cnt[base + d4.w], 1);
}

// ---------------- single-launch scan (grid barrier; 196 blocks all resident)
__global__ __launch_bounds__(1024) void scan_fused_kernel() {
    __shared__ int warpsum[32];
    __shared__ int s2[256];
    int b = blockIdx.x, t = threadIdx.x;
    int lane = t & 31, wid = t >> 5;
    int i = b * 1024 + t;
    int c = (i < VN) ? g_cnt[i] : 0;

    int v = c;
    #pragma unroll
    for (int off = 1; off < 32; off <<= 1) {
        int u = __shfl_up_sync(0xFFFFFFFFu, v, off);
        if (lane >= off) v += u;
    }
    if (lane == 31) warpsum[wid] = v;
    __syncthreads();
    if (wid == 0) {
        int wv = warpsum[lane];
        #pragma unroll
        for (int off = 1; off < 32; off <<= 1) {
            int u = __shfl_up_sync(0xFFFFFFFFu, wv, off);
            if (lane >= off) wv += u;
        }
        warpsum[lane] = wv;
    }
    __syncthreads();
    int incl_local = v + ((wid > 0) ? warpsum[wid - 1] : 0);
    int total = warpsum[31];

    if (t == 0) {
        g_blksum[b] = total;
        __threadfence();
        atomicAdd(&g_arrive, 1);
        while (atomicAdd(&g_arrive, 0) < NBLK2) { }
    }
    __syncthreads();

    if (t < 256) s2[t] = (t < NBLK2) ? g_blksum[t] : 0;
    __syncthreads();
    #pragma unroll
    for (int off = 1; off < 256; off <<= 1) {
        int u = 0;
        if (t < 256 && t >= off) u = s2[t - off];
        __syncthreads();
        if (t < 256) s2[t] += u;
        __syncthreads();
    }
    int prev = (b > 0) ? s2[b - 1] : 0;
    if (i < VN) {
        int incl = incl_local + prev;
        g_rowptr[i + 1] = incl;
        g_wp[i] = incl - c;
    }
    if (i == 0) g_rowptr[0] = 0;
}

// ------- standalone tf32 GEMM, 3-stage cp.async pipeline (runs on s2) -------
__global__ __launch_bounds__(256) void gemm_kernel(const float* __restrict__ X,
                                                   const float* __restrict__ bias) {
    __shared__ __align__(16) float Xs[3][128][20];
    __shared__ __align__(16) float Ws[3][16][72];

    int tid = threadIdx.x;
    int lane = tid & 31;
    int gid = lane >> 2, tig = lane & 3;
    int m0 = (tid >> 5) * 16;
    int n0 = blockIdx.x * 128;

    int xr0 = tid >> 2,          xs0 = tid & 3;
    int xr1 = (tid + 256) >> 2,  xs1 = xs0;
    int wk  = tid >> 4,          ws  = tid & 15;

    float acc[8][4];
    #pragma unroll
    for (int nt = 0; nt < 8; nt++)
        #pragma unroll
        for (int q = 0; q < 4; q++) acc[nt][q] = 0.f;

    int gn0 = n0 + xr0, gn1 = n0 + xr1;
    const float* xsrc0 = X + (size_t)((gn0 < NN) ? gn0 : 0) * FF + xs0 * 4;
    const float* xsrc1 = X + (size_t)((gn1 < NN) ? gn1 : 0) * FF + xs1 * 4;
    int sz0 = (gn0 < NN) ? 16 : 0;
    int sz1 = (gn1 < NN) ? 16 : 0;
    const float* wsrc = g_w1t + wk * HH + ws * 4;

    #pragma unroll
    for (int p = 0; p < 2; p++) {
        int k0 = p * 16;
        cp_async16(&Xs[p][xr0][xs0 * 4], xsrc0 + k0, sz0);
        cp_async16(&Xs[p][xr1][xs1 * 4], xsrc1 + k0, sz1);
        cp_async16(&Ws[p][wk][ws * 4], wsrc + (size_t)k0 * HH, 16);
        asm volatile("cp.async.commit_group;");
    }

    #pragma unroll 1
    for (int t = 0; t < NTILES; t++) {
        int s = t % 3;
        asm volatile("cp.async.wait_group 1;");
        __syncthreads();
        if (t + 2 < NTILES) {
            int sn = (t + 2) % 3;
            int k0 = (t + 2) * 16;
            cp_async16(&Xs[sn][xr0][xs0 * 4], xsrc0 + k0, sz0);
            cp_async16(&Xs[sn][xr1][xs1 * 4], xsrc1 + k0, sz1);
            cp_async16(&Ws[sn][wk][ws * 4], wsrc + (size_t)k0 * HH, 16);
        }
        asm volatile("cp.async.commit_group;");

        #pragma unroll
        for (int ks = 0; ks < 2; ks++) {
            unsigned a[4];
            a[0] = f2tf32(Xs[s][m0 + gid    ][ks * 8 + tig    ]);
            a[1] = f2tf32(Xs[s][m0 + gid + 8][ks * 8 + tig    ]);
            a[2] = f2tf32(Xs[s][m0 + gid    ][ks * 8 + tig + 4]);
            a[3] = f2tf32(Xs[s][m0 + gid + 8][ks * 8 + tig + 4]);
            #pragma unroll
            for (int nt = 0; nt < 8; nt++) {
                unsigned b0 = __float_as_uint(Ws[s][ks * 8 + tig    ][nt * 8 + gid]);
                unsigned b1 = __float_as_uint(Ws[s][ks * 8 + tig + 4][nt * 8 + gid]);
                mma_tf32(acc[nt], a, b0, b1);
            }
        }
    }

    #pragma unroll
    for (int rr = 0; rr < 2; rr++) {
        int row = n0 + m0 + rr * 8 + gid;
        if (row >= NN) continue;
        #pragma unroll
        for (int nt = 0; nt < 8; nt++) {
            int col = nt * 8 + 2 * tig;
            float v0 = fmaxf(acc[nt][rr * 2 + 0] + bias[col], 0.f);
            float v1 = fmaxf(acc[nt][rr * 2 + 1] + bias[col + 1], 0.f);
            *(float2*)(g_hidden + (size_t)row * HH + col) = make_float2(v0, v1);
        }
    }
}

// ---------------- standalone CSR scatter (30 regs, 86% occ — measured) ------
__global__ __launch_bounds__(256) void scatter_kernel(
        const int* __restrict__ src, const int* __restrict__ dst,
        const float* __restrict__ e_edge) {
    int t = blockIdx.x * 256 + threadIdx.x;            // covers 4 edges
    int4   s4 = ((const int4*)src)[t];
    int4   d4 = ((const int4*)dst)[t];
    float4 e0 = ((const float4*)e_edge)[t];
    float4 e1 = ((const float4*)(e_edge + 2 * (size_t)EE))[t];
    int base = ((t << 2) >= EE) ? NN : 0;
    // softmax max-shift cancels; exp(|e|<6) safe; fp16 range ok (exp<=e^6~403)
    if (!is_train(d4.x)) {
        int p = atomicAdd(&g_wp[base + d4.x], 1);
        __half2 w = __floats2half2_rn(__expf(e0.x), __expf(e1.x));
        g_edge8[p] = make_uint2((unsigned)s4.x, *(unsigned*)&w);
    }
    if (!is_train(d4.y)) {
        int p = atomicAdd(&g_wp[base + d4.y], 1);
        __half2 w = __floats2half2_rn(__expf(e0.y), __expf(e1.y));
        g_edge8[p] = make_uint2((unsigned)s4.y, *(unsigned*)&w);
    }
    if (!is_train(d4.z)) {
        int p = atomicAdd(&g_wp[base + d4.z], 1);
        __half2 w = __floats2half2_rn(__expf(e0.z), __expf(e1.z));
        g_edge8[p] = make_uint2((unsigned)s4.z, *(unsigned*)&w);
    }
    if (!is_train(d4.w)) {
        int p = atomicAdd(&g_wp[base + d4.w], 1);
        __half2 w = __floats2half2_rn(__expf(e0.w), __expf(e1.w));
        g_edge8[p] = make_uint2((unsigned)s4.w, *(unsigned*)&w);
    }
}

// ---- propagate (gather, warp-per-vnode, 2 lanes/edge, dual-edge MLP) -------
template <int LAYER>
__global__ __launch_bounds__(256) void prop_kernel(const float* __restrict__ one_hot) {
    int v    = (blockIdx.x * blockDim.x + threadIdx.x) >> 5;
    int lane = threadIdx.x & 31;
    if (v >= VN) return;
    int n = (v < NN) ? v : v - NN;

    if (is_train(n)) {
        if (LAYER == 0) {
            if (lane < 2) g_h016[(size_t)v * 2 + lane] = g_oh16[(size_t)n * 2 + lane];
        } else {
            if (lane < CC) g_hg[(size_t)v * CC + lane] = one_hot[(size_t)n * CC + lane];
        }
        return;
    }

    const uint4* hbase = (LAYER == 0) ? g_li16
                                      : (g_h016 + ((v < NN) ? 0 : (size_t)NN * 2));
    int beg = g_rowptr[v], end = g_rowptr[v + 1];
    int half = lane & 1;

    float a[8];
    #pragma unroll
    for (int q = 0; q < 8; q++) a[q] = 0.f;
    float sw = 0.f;

    for (int j = beg + (lane >> 1); j < end; j += 32) {
        uint2 r1 = g_edge8[j];
        int j2 = j + 16;
        uint2 r2 = (j2 < end) ? g_edge8[j2] : make_uint2(r1.x, 0u);  // w=0 pad
        int s1 = (int)r1.x, s2 = (int)r2.x;
        __half2 wh1 = *(__half2*)&r1.y, wh2 = *(__half2*)&r2.y;
        float w1 = (LAYER == 0) ? __low2float(wh1) : __high2float(wh1);
        float w2 = (LAYER == 0) ? __low2float(wh2) : __high2float(wh2);
        uint4 u1 = hbase[(size_t)s1 * 2 + half];
        uint4 u2 = hbase[(size_t)s2 * 2 + half];
        {
            float2 f0 = __half22float2(*(__half2*)&u1.x);
            float2 f1 = __half22float2(*(__half2*)&u1.y);
            float2 f2 = __half22float2(*(__half2*)&u1.z);
            float2 f3 = __half22float2(*(__half2*)&u1.w);
            a[0] = fmaf(w1, f0.x, a[0]); a[1] = fmaf(w1, f0.y, a[1]);
            a[2] = fmaf(w1, f1.x, a[2]); a[3] = fmaf(w1, f1.y, a[3]);
            a[4] = fmaf(w1, f2.x, a[4]); a[5] = fmaf(w1, f2.y, a[5]);
            a[6] = fmaf(w1, f3.x, a[6]); a[7] = fmaf(w1, f3.y, a[7]);
        }
        {
            float2 f0 = __half22float2(*(__half2*)&u2.x);
            float2 f1 = __half22float2(*(__half2*)&u2.y);
            float2 f2 = __half22float2(*(__half2*)&u2.z);
            float2 f3 = __half22float2(*(__half2*)&u2.w);
            a[0] = fmaf(w2, f0.x, a[0]); a[1] = fmaf(w2, f0.y, a[1]);
            a[2] = fmaf(w2, f1.x, a[2]); a[3] = fmaf(w2, f1.y, a[3]);
            a[4] = fmaf(w2, f2.x, a[4]); a[5] = fmaf(w2, f2.y, a[5]);
            a[6] = fmaf(w2, f3.x, a[6]); a[7] = fmaf(w2, f3.y, a[7]);
        }
        sw += w1 + w2;
    }
    #pragma unroll
    for (int off = 2; off < 32; off <<= 1) {
        #pragma unroll
        for (int q = 0; q < 8; q++)
            a[q] += __shfl_xor_sync(0xFFFFFFFFu, a[q], off);
        sw += __shfl_xor_sync(0xFFFFFFFFu, sw, off);
    }
    if (lane < 2) {
        float inv = (sw > 0.f) ? (1.f / sw) : 0.f;
        #pragma unroll
        for (int q = 0; q < 8; q++) a[q] *= inv;
        if (LAYER == 0) {
            __half2 o0 = __floats2half2_rn(a[0], a[1]);
            __half2 o1 = __floats2half2_rn(a[2], a[3]);
            __half2 o2 = __floats2half2_rn(a[4], a[5]);
            __half2 o3 = __floats2half2_rn(a[6], a[7]);
            uint4 u;
            u.x = *(unsigned*)&o0; u.y = *(unsigned*)&o1;
            u.z = *(unsigned*)&o2; u.w = *(unsigned*)&o3;
            g_h016[(size_t)v * 2 + half] = u;
        } else {
            float* op = g_hg + (size_t)v * CC + half * 8;
            ((float4*)op)[0] = make_float4(a[0], a[1], a[2], a[3]);
            ((float4*)op)[1] = make_float4(a[4], a[5], a[6], a[7]);
        }
    }
}

// ---------------- final: MLP layer 2 + attention combine + output -----------
__global__ __launch_bounds__(256) void final_kernel(const float* __restrict__ w2,
                                                    const float* __restrict__ b2,
                                                    const float* __restrict__ att,
                                                    const float* __restrict__ alpha,
                                                    float* __restrict__ out) {
    __shared__ float sw2[HH * CC];
    for (int i = threadIdx.x; i < HH * CC; i += blockDim.x) sw2[i] = w2[i];
    __syncthreads();
    int idx = blockIdx.x * blockDim.x + threadIdx.x;
    if (idx >= NN * CC) return;
    int n = idx >> 4, c = idx & 15;

    float m = b2[c];
    const float4* hr = (const float4*)(g_hidden + (size_t)n * HH);
    #pragma unroll
    for (int k = 0; k < 16; k++) {
        float4 hv = hr[k];
        m = fmaf(hv.x, sw2[(4 * k + 0) * CC + c], m);
        m = fmaf(hv.y, sw2[(4 * k + 1) * CC + c], m);
        m = fmaf(hv.z, sw2[(4 * k + 2) * CC + c], m);
        m = fmaf(hv.w, sw2[(4 * k + 3) * CC + c], m);
    }

    float a0 = att[n * 2 + 0], a1 = att[n * 2 + 1];
    float mx = fmaxf(a0, a1);
    float e0 = expf(a0 - mx), e1 = expf(a1 - mx);
    float inv = 1.f / (e0 + e1);

    float sa = 1.f / (1.f + expf(-alpha[n]));
    float logits = g_hg[idx] * (e0 * inv) + g_hg[(size_t)(NN + n) * CC + c] * (e1 * inv);
    out[idx] = sa * logits + (1.f - sa) * m;
}

// ---------------- launcher: fork-join capture (gemm on side stream) ---------
extern "C" void kernel_launch(void* const* d_in, const int* in_sizes, int n_in,
                              void* d_out, int out_size) {
    (void)in_sizes; (void)n_in; (void)out_size;
    const float* features   = (const float*)d_in[0];
    const float* label_init = (const float*)d_in[1];
    const float* one_hot    = (const float*)d_in[2];
    const float* alpha      = (const float*)d_in[3];
    const float* attention  = (const float*)d_in[4];
    const float* e_edge     = (const float*)d_in[5];
    const float* w1         = (const float*)d_in[6];
    const float* b1         = (const float*)d_in[7];
    const float* w2         = (const float*)d_in[8];
    const float* b2         = (const float*)d_in[9];
    const int*   src        = (const int*)d_in[10];
    const int*   dst        = (const int*)d_in[11];
    const int*   train      = (const int*)d_in[12];
    float*       out        = (float*)d_out;

    // Side stream + fork/join events. Created per call; NOT destroyed here —
    // destroying a forked stream mid-capture invalidates the capture. These
    // are host-side handles (no device memory), leaked a handful of times.
    cudaStream_t s2 = 0;
    cudaEvent_t evA = 0, evB = 0;
    bool forked = (cudaStreamCreateWithFlags(&s2, cudaStreamNonBlocking) == cudaSuccess) &&
                  (cudaEventCreateWithFlags(&evA, cudaEventDisableTiming) == cudaSuccess) &&
                  (cudaEventCreateWithFlags(&evB, cudaEventDisableTiming) == cudaSuccess);
    if (!forked) s2 = 0;

    prep_kernel<<<CONVB, 256>>>(train, w1, label_init, one_hot);          // main

    if (forked) {
        cudaEventRecord(evA, 0);
        cudaStreamWaitEvent(s2, evA, 0);
    }
    gemm_kernel<<<GEMM_BLKS, 256, 0, s2>>>(features, b1);                 // side

    hist_kernel<<<EB4, 256>>>(dst);                                       // main
    scan_fused_kernel<<<NBLK2, 1024>>>();                                 // main
    scatter_kernel<<<EB4, 256>>>(src, dst, e_edge);                       // main
    prop_kernel<0><<<PB2, 256>>>(one_hot);                                // main
    prop_kernel<1><<<PB2, 256>>>(one_hot);                                // main

    if (forked) {
        cudaEventRecord(evB, s2);
        cudaStreamWaitEvent(0, evB, 0);                                   // join
    }
    final_kernel<<<FB, 256>>>(w2, b2, attention, alpha, out);             // main
}